// round 3
// baseline (speedup 1.0000x reference)
#include <cuda_runtime.h>
#include <math.h>

#define Bm 512
#define Sm 64
#define Dm 128
#define NHm 4
#define DHm 32
#define Tm (Bm*Sm)
#define EPSm 1e-5f

// ---------------- scratch (static device globals; no allocation) ----------------
__device__ float g_h[Tm*Dm];                    // residual stream (B,S,D)
__device__ float g_xn[Tm*Dm];                   // LN output
__device__ float g_y[Tm*Dm];                    // scan output (B,S,D)
__device__ float g_gx[(size_t)Sm*Bm*512];       // gate precompute [s][b][n*128+g*32+k]

// ---------------- f32x2 packed math helpers ----------------
__device__ __forceinline__ unsigned long long pk2(float a, float b){
    unsigned long long r;
    asm("mov.b64 %0, {%1,%2};" : "=l"(r) : "f"(a), "f"(b));
    return r;
}
__device__ __forceinline__ void upk2(unsigned long long v, float &a, float &b){
    asm("mov.b64 {%0,%1}, %2;" : "=f"(a), "=f"(b) : "l"(v));
}
__device__ __forceinline__ unsigned long long fma2_(unsigned long long a, unsigned long long b, unsigned long long c){
    unsigned long long d;
    asm("fma.rn.f32x2 %0, %1, %2, %3;" : "=l"(d) : "l"(a), "l"(b), "l"(c));
    return d;
}

// ---------------- embedding ----------------
__global__ void k_embed(const int* __restrict__ x, const float* __restrict__ emb){
    int i = blockIdx.x*blockDim.x + threadIdx.x;   // over Tm*32 float4s
    int t = i >> 5, d4 = i & 31;
    int v = x[t];
    reinterpret_cast<float4*>(g_h)[t*32 + d4] =
        reinterpret_cast<const float4*>(emb)[v*32 + d4];
}

// ---------------- layernorm h -> xn ----------------
__global__ void k_ln(const float* __restrict__ w){
    int gt = blockIdx.x*8 + (threadIdx.x>>5);
    int lane = threadIdx.x & 31;
    float4 v = reinterpret_cast<const float4*>(g_h + (size_t)gt*Dm)[lane];
    float s = v.x+v.y+v.z+v.w;
    float q = v.x*v.x+v.y*v.y+v.z*v.z+v.w*v.w;
    #pragma unroll
    for (int o=16;o>0;o>>=1){ s += __shfl_xor_sync(0xffffffffu,s,o); q += __shfl_xor_sync(0xffffffffu,q,o); }
    float mu = s*(1.f/128.f);
    float inv = rsqrtf(q*(1.f/128.f) - mu*mu + EPSm);
    float4 wv = reinterpret_cast<const float4*>(w)[lane];
    float4 r;
    r.x=(v.x-mu)*inv*wv.x; r.y=(v.y-mu)*inv*wv.y;
    r.z=(v.z-mu)*inv*wv.z; r.w=(v.w-mu)*inv*wv.w;
    reinterpret_cast<float4*>(g_xn + (size_t)gt*Dm)[lane] = r;
}

// ---------------- gate precompute: gx[s,b,n,g,k] = sum_h xn[b,s,n*32+h]*Wg[g,n,k,h] ----------------
// shared: Wgs transposed to [n][h][g*32+k] (16384 f), xn tile 64 tokens (8192 f)
__global__ void k_gx(const float* __restrict__ wg){
    extern __shared__ float sm[];
    float* Wgs = sm;
    float* xns = sm + 16384;
    int tid = threadIdx.x;
    for (int j = tid; j < 16384; j += 256){
        int h = j & 31, k = (j>>5)&31, n = (j>>10)&3, g = j>>12;
        Wgs[(n*32+h)*128 + g*32 + k] = wg[j];
    }
    int t0 = blockIdx.x * 64;
    for (int j = tid; j < 64*128; j += 256) xns[j] = g_xn[(size_t)t0*Dm + j];
    __syncthreads();

    int half = tid >> 7;
    int o = tid & 127;
    int n = o >> 5, g = (o>>3)&3, k4 = (o&7)*4;
    const float* wbase = &Wgs[n*32*128 + g*32 + k4];

    for (int ch = 0; ch < 4; ch++){
        int tk0 = half*32 + ch*8;
        float4 acc[8];
        #pragma unroll
        for (int tt=0; tt<8; tt++) acc[tt] = make_float4(0.f,0.f,0.f,0.f);
        #pragma unroll 4
        for (int h=0; h<32; h++){
            float4 w4 = *reinterpret_cast<const float4*>(wbase + h*128);
            #pragma unroll
            for (int tt=0; tt<8; tt++){
                float xv = xns[(tk0+tt)*128 + n*32 + h];
                acc[tt].x += xv*w4.x; acc[tt].y += xv*w4.y;
                acc[tt].z += xv*w4.z; acc[tt].w += xv*w4.w;
            }
        }
        #pragma unroll
        for (int tt=0; tt<8; tt++){
            int t = t0 + tk0 + tt;
            int b = t >> 6, s = t & 63;
            *reinterpret_cast<float4*>(&g_gx[((size_t)(s*Bm + b))*512 + n*128 + g*32 + k4]) = acc[tt];
        }
    }
}

// ---------------- sequential sLSTM scan ----------------
// 2 batches per CTA. shared: R transposed to [n][h][k][g] (16384 f) + h state (256 f)
__global__ void k_scan(const float* __restrict__ Rw, const float* __restrict__ bw){
    extern __shared__ float sm[];
    float* Rs = sm;
    float* hs = sm + 16384;
    int tid = threadIdx.x;
    for (int j = tid; j < 16384; j += 256){
        int kk = j & 127, nh = j >> 7;
        int g = kk >> 5, k = kk & 31;
        Rs[nh*128 + k*4 + g] = Rw[j];
    }
    int slot = tid >> 7, o = tid & 127;
    int n = o >> 5, k = o & 31;
    int b = blockIdx.x*2 + slot;
    hs[slot*128 + o] = 0.f;
    float bias0 = bw[(n*4+0)*32+k];
    float bias1 = bw[(n*4+1)*32+k];
    float bias2 = bw[(n*4+2)*32+k];
    float bias3 = bw[(n*4+3)*32+k];
    float c = 0.f, nn = 0.f, m = 0.f;
    const float* rb = &Rs[n*32*128 + k*4];

    for (int s = 0; s < Sm; s++){
        __syncthreads();   // hs published from previous step
        size_t gxb = ((size_t)(s*Bm + b))*512 + n*128 + k;
        float gx0 = g_gx[gxb], gx1 = g_gx[gxb+32], gx2 = g_gx[gxb+64], gx3 = g_gx[gxb+96];
        float4 acc = make_float4(0.f,0.f,0.f,0.f);
        const float* hb = &hs[slot*128 + n*32];
        #pragma unroll
        for (int h = 0; h < 32; h++){
            float hv = hb[h];
            float4 r4 = *reinterpret_cast<const float4*>(rb + h*128);
            acc.x += hv*r4.x; acc.y += hv*r4.y; acc.z += hv*r4.z; acc.w += hv*r4.w;
        }
        float i_r = acc.x + gx0 + bias0;
        float f_r = acc.y + gx1 + bias1;
        float z_r = acc.z + gx2 + bias2;
        float o_r = acc.w + gx3 + bias3;
        // stable log-sigmoid
        float lsf = (f_r >= 0.f) ? (-__logf(1.f + __expf(-f_r)))
                                 : (f_r - __logf(1.f + __expf(f_r)));
        float lfm = m + lsf;
        float mnew = fmaxf(i_r, lfm);
        float ig = __expf(i_r - mnew);
        float fg = __expf(lfm - mnew);
        float e2z = __expf(2.f*z_r);
        float tz = 1.f - 2.f/(e2z + 1.f);       // tanh(z)
        c  = fg*c  + ig*tz;
        nn = fg*nn + ig;
        m  = mnew;
        float sig_o = 1.f/(1.f + __expf(-o_r));
        float hn = sig_o * c / nn;
        __syncthreads();   // everyone done reading hs
        hs[slot*128 + o] = hn;
        g_y[((size_t)(b*Sm + s))*Dm + o] = hn;
    }
}

// ---------------- multi-head groupnorm + residual into h ----------------
__global__ void k_gn(const float* __restrict__ w){
    int gt = blockIdx.x*8 + (threadIdx.x>>5);
    int lane = threadIdx.x & 31;
    float4 v = reinterpret_cast<const float4*>(g_y + (size_t)gt*Dm)[lane];
    float s = v.x+v.y+v.z+v.w;
    float q = v.x*v.x+v.y*v.y+v.z*v.z+v.w*v.w;
    #pragma unroll
    for (int o=1;o<8;o<<=1){ s += __shfl_xor_sync(0xffffffffu,s,o); q += __shfl_xor_sync(0xffffffffu,q,o); }
    float mu = s*(1.f/32.f);
    float inv = rsqrtf(q*(1.f/32.f) - mu*mu + EPSm);
    float4 wv = reinterpret_cast<const float4*>(w)[lane];
    float4 hv = reinterpret_cast<const float4*>(g_h + (size_t)gt*Dm)[lane];
    hv.x += (v.x-mu)*inv*wv.x; hv.y += (v.y-mu)*inv*wv.y;
    hv.z += (v.z-mu)*inv*wv.z; hv.w += (v.w-mu)*inv*wv.w;
    reinterpret_cast<float4*>(g_h + (size_t)gt*Dm)[lane] = hv;
}

// ---------------- fused LN2 + GeGLU FF + residual ----------------
#define WUPS 257
#define WDNS 129
__global__ void k_ff(const float* __restrict__ ln2w, const float* __restrict__ wup,
                     const float* __restrict__ wdn){
    extern __shared__ float sm[];
    float* Wup_s = sm;                    // [j][o] padded stride 257, 128x256
    float* Wdn_s = sm + 128*WUPS;         // [j][d] padded stride 129, 128x128
    float* xns   = Wdn_s + 128*WDNS;      // [j][t] 128x8
    float* vs    = xns + 1024;            // [j][t] 128x8
    int tid = threadIdx.x;
    for (int j2 = tid; j2 < 256*128; j2 += 128){
        int oo = j2 >> 7, j = j2 & 127;
        Wup_s[j*WUPS + oo] = wup[j2];
    }
    for (int j2 = tid; j2 < 128*128; j2 += 128){
        int dd = j2 >> 7, j = j2 & 127;
        Wdn_s[j*WDNS + dd] = wdn[j2];
    }
    __syncthreads();
    int wid = tid >> 5, lane = tid & 31;
    int t0 = blockIdx.x * 128;

    for (int grp = 0; grp < 16; grp++){
        int tg = t0 + grp*8;
        // LN2 of 8 tokens (warp per token, 2 passes)
        #pragma unroll
        for (int pass = 0; pass < 2; pass++){
            int tok = pass*4 + wid;
            float4 v = reinterpret_cast<const float4*>(g_h + (size_t)(tg+tok)*Dm)[lane];
            float s = v.x+v.y+v.z+v.w;
            float q = v.x*v.x+v.y*v.y+v.z*v.z+v.w*v.w;
            #pragma unroll
            for (int o=16;o>0;o>>=1){ s += __shfl_xor_sync(0xffffffffu,s,o); q += __shfl_xor_sync(0xffffffffu,q,o); }
            float mu = s*(1.f/128.f);
            float inv = rsqrtf(q*(1.f/128.f)-mu*mu+EPSm);
            float4 wv = reinterpret_cast<const float4*>(ln2w)[lane];
            xns[(lane*4+0)*8 + tok] = (v.x-mu)*inv*wv.x;
            xns[(lane*4+1)*8 + tok] = (v.y-mu)*inv*wv.y;
            xns[(lane*4+2)*8 + tok] = (v.z-mu)*inv*wv.z;
            xns[(lane*4+3)*8 + tok] = (v.w-mu)*inv*wv.w;
        }
        __syncthreads();
        // up-proj (gate = row tid, value = row tid+128) + GELU, f32x2 over token pairs
        {
            unsigned long long aG[4], aU[4];
            #pragma unroll
            for (int p=0;p<4;p++){ aG[p]=0ull; aU[p]=0ull; }
            const float* wup0 = Wup_s + tid;
            const float* wup1 = Wup_s + tid + 128;
            #pragma unroll 4
            for (int j = 0; j < 128; j++){
                float wgv = wup0[j*WUPS], wuv = wup1[j*WUPS];
                unsigned long long wg2 = pk2(wgv,wgv), wu2 = pk2(wuv,wuv);
                const unsigned long long* xp = reinterpret_cast<const unsigned long long*>(xns + j*8);
                #pragma unroll
                for (int p=0;p<4;p++){
                    unsigned long long x2 = xp[p];
                    aG[p] = fma2_(x2, wg2, aG[p]);
                    aU[p] = fma2_(x2, wu2, aU[p]);
                }
            }
            float vout[8];
            #pragma unroll
            for (int p=0;p<4;p++){
                float ga,gb,ua,ub; upk2(aG[p],ga,gb); upk2(aU[p],ua,ub);
                vout[2*p]   = 0.5f*ga*(1.f+erff(ga*0.70710678118f))*ua;
                vout[2*p+1] = 0.5f*gb*(1.f+erff(gb*0.70710678118f))*ub;
            }
            float4* vp = reinterpret_cast<float4*>(vs + tid*8);
            vp[0] = make_float4(vout[0],vout[1],vout[2],vout[3]);
            vp[1] = make_float4(vout[4],vout[5],vout[6],vout[7]);
        }
        __syncthreads();
        // down-proj + residual, f32x2 over token pairs
        {
            unsigned long long aD[4];
            #pragma unroll
            for (int p=0;p<4;p++) aD[p]=0ull;
            const float* wd = Wdn_s + tid;
            #pragma unroll 4
            for (int j = 0; j < 128; j++){
                float w = wd[j*WDNS];
                unsigned long long w2 = pk2(w,w);
                const unsigned long long* vp = reinterpret_cast<const unsigned long long*>(vs + j*8);
                #pragma unroll
                for (int p=0;p<4;p++) aD[p] = fma2_(vp[p], w2, aD[p]);
            }
            #pragma unroll
            for (int p=0;p<4;p++){
                float a,bv; upk2(aD[p],a,bv);
                g_h[(size_t)(tg + 2*p)*Dm + tid]   += a;
                g_h[(size_t)(tg + 2*p+1)*Dm + tid] += bv;
            }
        }
        __syncthreads();
    }
}

// ---------------- final LN + vocab projection ----------------
__global__ void k_proj(const float* __restrict__ pw_ln, const float* __restrict__ pjw,
                       const float* __restrict__ pjb, float* __restrict__ out){
    int gt = blockIdx.x*8 + (threadIdx.x>>5);
    int lane = threadIdx.x & 31;
    float4 v = reinterpret_cast<const float4*>(g_h + (size_t)gt*Dm)[lane];
    float s = v.x+v.y+v.z+v.w;
    float q = v.x*v.x+v.y*v.y+v.z*v.z+v.w*v.w;
    #pragma unroll
    for (int o=16;o>0;o>>=1){ s += __shfl_xor_sync(0xffffffffu,s,o); q += __shfl_xor_sync(0xffffffffu,q,o); }
    float mu = s*(1.f/128.f);
    float inv = rsqrtf(q*(1.f/128.f) - mu*mu + EPSm);
    float4 wv = reinterpret_cast<const float4*>(pw_ln)[lane];
    float4 xv;
    xv.x=(v.x-mu)*inv*wv.x; xv.y=(v.y-mu)*inv*wv.y;
    xv.z=(v.z-mu)*inv*wv.z; xv.w=(v.w-mu)*inv*wv.w;
    float res = 0.f;
    #pragma unroll
    for (int vc = 0; vc < 9; vc++){
        float4 p = reinterpret_cast<const float4*>(pjw + vc*Dm)[lane];
        float sv = xv.x*p.x + xv.y*p.y + xv.z*p.z + xv.w*p.w;
        #pragma unroll
        for (int o=16;o>0;o>>=1) sv += __shfl_xor_sync(0xffffffffu,sv,o);
        if (lane == vc) res = sv;
    }
    if (lane < 9) out[gt*9 + lane] = res + pjb[lane];
}

// ---------------- launch ----------------
extern "C" void kernel_launch(void* const* d_in, const int* in_sizes, int n_in,
                              void* d_out, int out_size){
    const int*   x      = (const int*)  d_in[0];
    const float* emb    = (const float*)d_in[1];
    const float* ln1_w  = (const float*)d_in[2];
    const float* Wg     = (const float*)d_in[3];
    const float* R      = (const float*)d_in[4];
    const float* bias   = (const float*)d_in[5];
    const float* gn_w   = (const float*)d_in[6];
    const float* ln2_w  = (const float*)d_in[7];
    const float* ffu    = (const float*)d_in[8];
    const float* ffd    = (const float*)d_in[9];
    const float* post_w = (const float*)d_in[10];
    const float* pjw    = (const float*)d_in[11];
    const float* pjb    = (const float*)d_in[12];
    float* out = (float*)d_out;

    static_assert(sizeof(float4)==16, "f4");

    cudaFuncSetAttribute(k_gx,   cudaFuncAttributeMaxDynamicSharedMemorySize, (16384+8192)*4);
    cudaFuncSetAttribute(k_scan, cudaFuncAttributeMaxDynamicSharedMemorySize, (16384+256)*4);
    cudaFuncSetAttribute(k_ff,   cudaFuncAttributeMaxDynamicSharedMemorySize, (128*WUPS+128*WDNS+2048)*4);

    k_embed<<<4096,256>>>(x, emb);
    for (int bi = 0; bi < 2; bi++){
        k_ln  <<<4096,256>>>(ln1_w + bi*Dm);
        k_gx  <<<512,256,(16384+8192)*4>>>(Wg + bi*16384);
        k_scan<<<256,256,(16384+256)*4>>>(R + bi*16384, bias + bi*512);
        k_gn  <<<4096,256>>>(gn_w + bi*Dm);
        k_ff  <<<256,128,(128*WUPS+128*WDNS+2048)*4>>>(ln2_w + bi*Dm, ffu + bi*32768, ffd + bi*16384);
    }
    k_proj<<<4096,256>>>(post_w, pjw, pjb, out);
}

// round 4
// speedup vs baseline: 1.6677x; 1.6677x over previous
#include <cuda_runtime.h>
#include <math.h>

#define Bm 512
#define Sm 64
#define Dm 128
#define EPSm 1e-5f

typedef unsigned long long ull;

// ---------------- scratch ----------------
__device__ float g_h[Bm*Sm*Dm];                 // residual stream (B,S,D)
__device__ float g_gx[(size_t)Sm*Bm*512];       // gates [s][b][n][k][g]

// ---------------- f32x2 helpers ----------------
__device__ __forceinline__ ull pk2(float a, float b){
    ull r; asm("mov.b64 %0, {%1,%2};" : "=l"(r) : "f"(a), "f"(b)); return r;
}
__device__ __forceinline__ void upk2(ull v, float &a, float &b){
    asm("mov.b64 {%0,%1}, %2;" : "=f"(a), "=f"(b) : "l"(v));
}
__device__ __forceinline__ ull fma2_(ull a, ull b, ull c){
    ull d; asm("fma.rn.f32x2 %0, %1, %2, %3;" : "=l"(d) : "l"(a), "l"(b), "l"(c)); return d;
}

// ---------------- embedding ----------------
__global__ void k_embed(const int* __restrict__ x, const float* __restrict__ emb){
    int i = blockIdx.x*blockDim.x + threadIdx.x;   // Tm*32 float4s
    int t = i >> 5, d4 = i & 31;
    int v = x[t];
    reinterpret_cast<float4*>(g_h)[t*32 + d4] =
        reinterpret_cast<const float4*>(emb)[v*32 + d4];
}

// ---------------- fused LN1 + gate GEMM ----------------
// grid 512 (one CTA per batch), 256 threads
// smem: WgT [n][h][k*4+g] (16384 f) + xns [d][t] stride 66 (8448 f)
#define GX_SMEM ((16384 + 8448)*4)
__global__ void __launch_bounds__(256,2) k_gx(const float* __restrict__ wg,
                                              const float* __restrict__ lnw){
    extern __shared__ float sm[];
    float* Wgs = sm;
    float* xns = sm + 16384;
    int tid = threadIdx.x;
    // stage Wg transposed: src wg[((g*4+n)*32+k)*32+h]
    for (int j = tid; j < 16384; j += 256){
        int h = j & 31, k = (j>>5)&31, n = (j>>10)&3, g = j>>12;
        Wgs[n*4096 + h*128 + k*4 + g] = wg[j];
    }
    int wid = tid>>5, lane = tid&31;
    int b = blockIdx.x;               // 64 tokens == one batch (b, s=0..63)
    size_t h0 = (size_t)b*64*Dm;
    float4 lw = reinterpret_cast<const float4*>(lnw)[lane];
    // LN of 64 tokens: 8 warps x 8 tokens, write xns[d][t] (stride 66)
    for (int tt = 0; tt < 8; tt++){
        int tok = wid*8 + tt;
        float4 v = reinterpret_cast<const float4*>(g_h + h0 + (size_t)tok*Dm)[lane];
        float s = v.x+v.y+v.z+v.w;
        float q = v.x*v.x+v.y*v.y+v.z*v.z+v.w*v.w;
        #pragma unroll
        for (int o=16;o>0;o>>=1){ s += __shfl_xor_sync(0xffffffffu,s,o); q += __shfl_xor_sync(0xffffffffu,q,o); }
        float mu = s*(1.f/128.f);
        float inv = rsqrtf(q*(1.f/128.f) - mu*mu + EPSm);
        xns[(lane*4+0)*66 + tok] = (v.x-mu)*inv*lw.x;
        xns[(lane*4+1)*66 + tok] = (v.y-mu)*inv*lw.y;
        xns[(lane*4+2)*66 + tok] = (v.z-mu)*inv*lw.z;
        xns[(lane*4+3)*66 + tok] = (v.w-mu)*inv*lw.w;
    }
    __syncthreads();
    // compute: thread = (half, n, k)
    int o = tid & 127, n = o>>5, k = o&31, half = tid>>7;
    const float* wb = Wgs + n*4096 + k*4;
    for (int grp = 0; grp < 4; grp++){
        int tk0 = half*32 + grp*8;
        ull a0[4], a1[4], a2[4], a3[4];
        #pragma unroll
        for (int p=0;p<4;p++){ a0[p]=0; a1[p]=0; a2[p]=0; a3[p]=0; }
        #pragma unroll 8
        for (int h = 0; h < 32; h++){
            float4 w4 = *reinterpret_cast<const float4*>(wb + h*128);
            ull w0 = pk2(w4.x,w4.x), w1 = pk2(w4.y,w4.y);
            ull w2 = pk2(w4.z,w4.z), w3 = pk2(w4.w,w4.w);
            const ull* xp = reinterpret_cast<const ull*>(xns + (n*32+h)*66 + tk0);
            #pragma unroll
            for (int p=0;p<4;p++){
                ull x2 = xp[p];
                a0[p] = fma2_(x2, w0, a0[p]);
                a1[p] = fma2_(x2, w1, a1[p]);
                a2[p] = fma2_(x2, w2, a2[p]);
                a3[p] = fma2_(x2, w3, a3[p]);
            }
        }
        #pragma unroll
        for (int p=0;p<4;p++){
            float i0,i1,f0,f1,z0,z1,q0,q1;
            upk2(a0[p],i0,i1); upk2(a1[p],f0,f1); upk2(a2[p],z0,z1); upk2(a3[p],q0,q1);
            int s0 = tk0 + 2*p;
            size_t base0 = ((size_t)(s0*Bm + b))*512 + n*128 + k*4;
            size_t base1 = ((size_t)((s0+1)*Bm + b))*512 + n*128 + k*4;
            *reinterpret_cast<float4*>(&g_gx[base0]) = make_float4(i0,f0,z0,q0);
            *reinterpret_cast<float4*>(&g_gx[base1]) = make_float4(i1,f1,z1,q1);
        }
    }
}

// ---------------- sLSTM gate math ----------------
__device__ __forceinline__ float slstm_step(float i_r, float f_r, float z_r, float o_r,
                                            float& c, float& nn, float& m){
    float lsf = (f_r >= 0.f) ? (-__logf(1.f + __expf(-f_r)))
                             : (f_r - __logf(1.f + __expf(f_r)));
    float lfm = m + lsf;
    float mnew = fmaxf(i_r, lfm);
    float ig = __expf(i_r - mnew);
    float fg = __expf(lfm - mnew);
    float e2z = __expf(2.f*z_r);
    float tz = 1.f - 2.f/(e2z + 1.f);
    c  = fg*c  + ig*tz;
    nn = fg*nn + ig;
    m  = mnew;
    float so = 1.f/(1.f + __expf(-o_r));
    return so * c / nn;
}

// ---------------- sequential scan, R in registers, fused GN+residual ----------------
// grid 256, 128 threads, 2 batches/CTA, single wave (2 CTA/SM)
__global__ void __launch_bounds__(128,2) k_scan(const float* __restrict__ Rw,
                                                const float* __restrict__ bw,
                                                const float* __restrict__ gnw){
    __shared__ __align__(16) float hs[512];   // duplicated: [slot][o][2]
    int tid = threadIdx.x;
    int n = tid >> 5, k = tid & 31;
    int b0 = blockIdx.x*2, b1 = b0 + 1;

    // R slice into registers, packed (g0,g1) and (g2,g3)
    ull r01[32], r23[32];
    const float* rp = Rw + n*4096 + k;
    #pragma unroll
    for (int h = 0; h < 32; h++){
        r01[h] = pk2(rp[h*128],      rp[h*128 + 32]);
        r23[h] = pk2(rp[h*128 + 64], rp[h*128 + 96]);
    }
    float bias0 = bw[(n*4+0)*32+k], bias1 = bw[(n*4+1)*32+k];
    float bias2 = bw[(n*4+2)*32+k], bias3 = bw[(n*4+3)*32+k];
    float gw = gnw[n*32+k];

    int o = n*32 + k;
    *reinterpret_cast<ull*>(&hs[o*2])       = 0ull;
    *reinterpret_cast<ull*>(&hs[256 + o*2]) = 0ull;
    float ca=0.f, na=0.f, ma=0.f, cb=0.f, nb=0.f, mb=0.f;
    __syncthreads();

    for (int s = 0; s < Sm; s++){
        float4 ga = *reinterpret_cast<const float4*>(&g_gx[((size_t)(s*Bm + b0))*512 + n*128 + k*4]);
        float4 gb = *reinterpret_cast<const float4*>(&g_gx[((size_t)(s*Bm + b1))*512 + n*128 + k*4]);
        ull aa01=0, aa23=0, ab01=0, ab23=0;
        const ull* hpa = reinterpret_cast<const ull*>(&hs[n*64]);
        const ull* hpb = reinterpret_cast<const ull*>(&hs[256 + n*64]);
        #pragma unroll
        for (int h = 0; h < 32; h++){
            ull ha2 = hpa[h];
            ull hb2 = hpb[h];
            aa01 = fma2_(ha2, r01[h], aa01);
            aa23 = fma2_(ha2, r23[h], aa23);
            ab01 = fma2_(hb2, r01[h], ab01);
            ab23 = fma2_(hb2, r23[h], ab23);
        }
        float ria,rfa,rza,roa, rib,rfb,rzb,rob;
        upk2(aa01,ria,rfa); upk2(aa23,rza,roa);
        upk2(ab01,rib,rfb); upk2(ab23,rzb,rob);
        float hn_a = slstm_step(ria+ga.x+bias0, rfa+ga.y+bias1, rza+ga.z+bias2, roa+ga.w+bias3, ca,na,ma);
        float hn_b = slstm_step(rib+gb.x+bias0, rfb+gb.y+bias1, rzb+gb.z+bias2, rob+gb.w+bias3, cb,nb,mb);
        __syncthreads();   // all reads of hs done
        *reinterpret_cast<ull*>(&hs[o*2])       = pk2(hn_a, hn_a);
        *reinterpret_cast<ull*>(&hs[256 + o*2]) = pk2(hn_b, hn_b);
        // GroupNorm per (batch, head) == per warp, + residual into g_h
        float sa = hn_a, qa = hn_a*hn_a, sb = hn_b, qb = hn_b*hn_b;
        #pragma unroll
        for (int off=16; off>0; off>>=1){
            sa += __shfl_xor_sync(0xffffffffu,sa,off);
            qa += __shfl_xor_sync(0xffffffffu,qa,off);
            sb += __shfl_xor_sync(0xffffffffu,sb,off);
            qb += __shfl_xor_sync(0xffffffffu,qb,off);
        }
        float mua = sa*(1.f/32.f);
        float inva = rsqrtf(qa*(1.f/32.f) - mua*mua + EPSm);
        float mub = sb*(1.f/32.f);
        float invb = rsqrtf(qb*(1.f/32.f) - mub*mub + EPSm);
        g_h[(size_t)(b0*64+s)*Dm + o] += (hn_a - mua)*inva*gw;
        g_h[(size_t)(b1*64+s)*Dm + o] += (hn_b - mub)*invb*gw;
        __syncthreads();   // hs writes visible
    }
}

// ---------------- fused LN2 + GeGLU FF + residual ----------------
// grid 128, 512 threads, 256 tokens/CTA
#define XST 34
#define FF_SMEM ((32768 + 16384 + 128*XST*2)*4)
__global__ void __launch_bounds__(512,1) k_ff(const float* __restrict__ ln2w,
                                              const float* __restrict__ wup,
                                              const float* __restrict__ wdn){
    extern __shared__ float sm[];
    float* Wup_s = sm;                 // [j][r*2 + which] stride 256
    float* Wdn_s = sm + 32768;         // [j][d] stride 128
    float* xns   = Wdn_s + 16384;      // [j][t] stride 34
    float* vs    = xns + 128*XST;      // [j][t] stride 34
    int tid = threadIdx.x;
    for (int idx = tid; idx < 32768; idx += 512){
        int oo = idx >> 7, j = idx & 127;
        Wup_s[j*256 + (oo&127)*2 + (oo>>7)] = wup[idx];
    }
    for (int idx = tid; idx < 16384; idx += 512){
        int dd = idx >> 7, j = idx & 127;
        Wdn_s[j*128 + dd] = wdn[idx];
    }
    __syncthreads();
    int r = tid & 127, q = tid >> 7;
    int wid = tid >> 5, lane = tid & 31;
    int t0 = blockIdx.x * 256;
    float4 lw = reinterpret_cast<const float4*>(ln2w)[lane];

    for (int it = 0; it < 8; it++){
        int tg = t0 + it*32;
        // LN: 16 warps x 2 tokens
        #pragma unroll
        for (int pp = 0; pp < 2; pp++){
            int tok = pp*16 + wid;
            float4 v = reinterpret_cast<const float4*>(g_h + (size_t)(tg+tok)*Dm)[lane];
            float s = v.x+v.y+v.z+v.w;
            float qq = v.x*v.x+v.y*v.y+v.z*v.z+v.w*v.w;
            #pragma unroll
            for (int of=16;of>0;of>>=1){ s += __shfl_xor_sync(0xffffffffu,s,of); qq += __shfl_xor_sync(0xffffffffu,qq,of); }
            float mu = s*(1.f/128.f);
            float inv = rsqrtf(qq*(1.f/128.f)-mu*mu+EPSm);
            xns[(lane*4+0)*XST + tok] = (v.x-mu)*inv*lw.x;
            xns[(lane*4+1)*XST + tok] = (v.y-mu)*inv*lw.y;
            xns[(lane*4+2)*XST + tok] = (v.z-mu)*inv*lw.z;
            xns[(lane*4+3)*XST + tok] = (v.w-mu)*inv*lw.w;
        }
        __syncthreads();
        // up-proj + GELU -> vs
        {
            ull aG[4], aU[4];
            #pragma unroll
            for (int p=0;p<4;p++){ aG[p]=0; aU[p]=0; }
            const float* wpp = Wup_s + r*2;
            const float* xpp = xns + q*8;
            #pragma unroll 4
            for (int j = 0; j < 128; j++){
                float2 wpr = *reinterpret_cast<const float2*>(wpp + j*256);
                ull wg2 = pk2(wpr.x, wpr.x), wu2 = pk2(wpr.y, wpr.y);
                const ull* xp = reinterpret_cast<const ull*>(xpp + j*XST);
                #pragma unroll
                for (int p=0;p<4;p++){
                    ull x2 = xp[p];
                    aG[p] = fma2_(x2, wg2, aG[p]);
                    aU[p] = fma2_(x2, wu2, aU[p]);
                }
            }
            float* vdst = vs + r*XST + q*8;
            #pragma unroll
            for (int p=0;p<4;p++){
                float ga,gb,ua,ub; upk2(aG[p],ga,gb); upk2(aU[p],ua,ub);
                float v0 = 0.5f*ga*(1.f+erff(ga*0.70710678118f))*ua;
                float v1 = 0.5f*gb*(1.f+erff(gb*0.70710678118f))*ub;
                *reinterpret_cast<ull*>(vdst + 2*p) = pk2(v0,v1);
            }
        }
        __syncthreads();
        // down-proj + residual
        {
            ull aD[4];
            #pragma unroll
            for (int p=0;p<4;p++) aD[p]=0;
            const float* wdp = Wdn_s + r;
            const float* vpp = vs + q*8;
            #pragma unroll 4
            for (int j = 0; j < 128; j++){
                float w = wdp[j*128];
                ull w2 = pk2(w,w);
                const ull* vp = reinterpret_cast<const ull*>(vpp + j*XST);
                #pragma unroll
                for (int p=0;p<4;p++) aD[p] = fma2_(vp[p], w2, aD[p]);
            }
            #pragma unroll
            for (int p=0;p<4;p++){
                float d0,d1; upk2(aD[p],d0,d1);
                int ta = tg + q*8 + 2*p;
                g_h[(size_t)ta*Dm + r]     += d0;
                g_h[(size_t)(ta+1)*Dm + r] += d1;
            }
        }
        __syncthreads();
    }
}

// ---------------- final LN + vocab projection ----------------
__global__ void k_proj(const float* __restrict__ pw_ln, const float* __restrict__ pjw,
                       const float* __restrict__ pjb, float* __restrict__ out){
    int gt = blockIdx.x*8 + (threadIdx.x>>5);
    int lane = threadIdx.x & 31;
    float4 v = reinterpret_cast<const float4*>(g_h + (size_t)gt*Dm)[lane];
    float s = v.x+v.y+v.z+v.w;
    float q = v.x*v.x+v.y*v.y+v.z*v.z+v.w*v.w;
    #pragma unroll
    for (int o=16;o>0;o>>=1){ s += __shfl_xor_sync(0xffffffffu,s,o); q += __shfl_xor_sync(0xffffffffu,q,o); }
    float mu = s*(1.f/128.f);
    float inv = rsqrtf(q*(1.f/128.f) - mu*mu + EPSm);
    float4 wv = reinterpret_cast<const float4*>(pw_ln)[lane];
    float4 xv;
    xv.x=(v.x-mu)*inv*wv.x; xv.y=(v.y-mu)*inv*wv.y;
    xv.z=(v.z-mu)*inv*wv.z; xv.w=(v.w-mu)*inv*wv.w;
    float res = 0.f;
    #pragma unroll
    for (int vc = 0; vc < 9; vc++){
        float4 p = reinterpret_cast<const float4*>(pjw + vc*Dm)[lane];
        float sv = xv.x*p.x + xv.y*p.y + xv.z*p.z + xv.w*p.w;
        #pragma unroll
        for (int o=16;o>0;o>>=1) sv += __shfl_xor_sync(0xffffffffu,sv,o);
        if (lane == vc) res = sv;
    }
    if (lane < 9) out[gt*9 + lane] = res + pjb[lane];
}

// ---------------- launch ----------------
extern "C" void kernel_launch(void* const* d_in, const int* in_sizes, int n_in,
                              void* d_out, int out_size){
    const int*   x      = (const int*)  d_in[0];
    const float* emb    = (const float*)d_in[1];
    const float* ln1_w  = (const float*)d_in[2];
    const float* Wg     = (const float*)d_in[3];
    const float* R      = (const float*)d_in[4];
    const float* bias   = (const float*)d_in[5];
    const float* gn_w   = (const float*)d_in[6];
    const float* ln2_w  = (const float*)d_in[7];
    const float* ffu    = (const float*)d_in[8];
    const float* ffd    = (const float*)d_in[9];
    const float* post_w = (const float*)d_in[10];
    const float* pjw    = (const float*)d_in[11];
    const float* pjb    = (const float*)d_in[12];
    float* out = (float*)d_out;

    cudaFuncSetAttribute(k_gx, cudaFuncAttributeMaxDynamicSharedMemorySize, GX_SMEM);
    cudaFuncSetAttribute(k_ff, cudaFuncAttributeMaxDynamicSharedMemorySize, FF_SMEM);

    k_embed<<<4096,256>>>(x, emb);
    for (int bi = 0; bi < 2; bi++){
        k_gx  <<<512,256,GX_SMEM>>>(Wg + bi*16384, ln1_w + bi*Dm);
        k_scan<<<256,128>>>(R + bi*16384, bias + bi*512, gn_w + bi*Dm);
        k_ff  <<<128,512,FF_SMEM>>>(ln2_w + bi*Dm, ffu + bi*32768, ffd + bi*16384);
    }
    k_proj<<<4096,256>>>(post_w, pjw, pjb, out);
}

// round 5
// speedup vs baseline: 1.9847x; 1.1901x over previous
#include <cuda_runtime.h>
#include <math.h>

#define Bm 512
#define Sm 64
#define Dm 128
#define EPSm 1e-5f

typedef unsigned long long ull;

// ---------------- scratch ----------------
__device__ float g_h[Bm*Sm*Dm];                 // residual stream (B,S,D)
__device__ float g_v[Bm*Sm*Dm];                 // gelu(gate)*up, [blk][j][tok64]
__device__ float g_gx[(size_t)Sm*Bm*512];       // gates [s][b][n][k][g]

// ---------------- f32x2 helpers ----------------
__device__ __forceinline__ ull pk2(float a, float b){
    ull r; asm("mov.b64 %0, {%1,%2};" : "=l"(r) : "f"(a), "f"(b)); return r;
}
__device__ __forceinline__ void upk2(ull v, float &a, float &b){
    asm("mov.b64 {%0,%1}, %2;" : "=f"(a), "=f"(b) : "l"(v));
}
__device__ __forceinline__ ull fma2_(ull a, ull b, ull c){
    ull d; asm("fma.rn.f32x2 %0, %1, %2, %3;" : "=l"(d) : "l"(a), "l"(b), "l"(c)); return d;
}

// ---------------- embedding ----------------
__global__ void k_embed(const int* __restrict__ x, const float* __restrict__ emb){
    int i = blockIdx.x*blockDim.x + threadIdx.x;
    int t = i >> 5, d4 = i & 31;
    int v = x[t];
    reinterpret_cast<float4*>(g_h)[t*32 + d4] =
        reinterpret_cast<const float4*>(emb)[v*32 + d4];
}

// ================= fused LN1 + gate GEMM =================
// grid 128, 512 threads, 4 batches per CTA
#define GXW_ST 132
#define GX_XST 68
#define GX_SMEM ((4*32*GXW_ST + 128*GX_XST)*4)
__global__ void __launch_bounds__(512,1) k_gx(const float* __restrict__ wg,
                                              const float* __restrict__ lnw){
    extern __shared__ float sm[];
    float* Wgs = sm;                      // [n][h*132 + k*4 + g]
    float* xns = sm + 4*32*GXW_ST;        // [d][t] stride 68
    int tid = threadIdx.x;
    for (int j = tid; j < 16384; j += 512){
        int h = j & 31, k = (j>>5)&31, n = (j>>10)&3, g = j>>12;
        Wgs[(n*32 + h)*GXW_ST + k*4 + g] = wg[j];
    }
    int wid = tid>>5, lane = tid&31;
    float4 lw = reinterpret_cast<const float4*>(lnw)[lane];
    int oid = tid & 127;
    int n = oid>>5, k = oid&31;
    int q = tid>>7;                       // 0..3
    int tk0 = q*16;
    const float* wb = Wgs + (n*32)*GXW_ST + k*4;

    for (int bb = 0; bb < 4; bb++){
        int b = blockIdx.x*4 + bb;
        size_t h0 = (size_t)b*64*Dm;
        __syncthreads();
        // LN of 64 tokens: 16 warps x 4 tokens
        #pragma unroll
        for (int pp = 0; pp < 4; pp++){
            int tok = pp*16 + wid;
            float4 v = reinterpret_cast<const float4*>(g_h + h0 + (size_t)tok*Dm)[lane];
            float s = v.x+v.y+v.z+v.w;
            float qq = v.x*v.x+v.y*v.y+v.z*v.z+v.w*v.w;
            #pragma unroll
            for (int o=16;o>0;o>>=1){ s += __shfl_xor_sync(0xffffffffu,s,o); qq += __shfl_xor_sync(0xffffffffu,qq,o); }
            float mu = s*(1.f/128.f);
            float inv = rsqrtf(qq*(1.f/128.f) - mu*mu + EPSm);
            xns[(lane*4+0)*GX_XST + tok] = (v.x-mu)*inv*lw.x;
            xns[(lane*4+1)*GX_XST + tok] = (v.y-mu)*inv*lw.y;
            xns[(lane*4+2)*GX_XST + tok] = (v.z-mu)*inv*lw.z;
            xns[(lane*4+3)*GX_XST + tok] = (v.w-mu)*inv*lw.w;
        }
        __syncthreads();
        ull acc0[8], acc1[8], acc2[8], acc3[8];
        #pragma unroll
        for (int p=0;p<8;p++){ acc0[p]=0; acc1[p]=0; acc2[p]=0; acc3[p]=0; }
        #pragma unroll 4
        for (int h = 0; h < 32; h++){
            float4 w4 = *reinterpret_cast<const float4*>(wb + h*GXW_ST);
            const ulonglong2* xp = reinterpret_cast<const ulonglong2*>(xns + (n*32+h)*GX_XST + tk0);
            ulonglong2 xa = xp[0], xb = xp[1], xc = xp[2], xd = xp[3];
            ull w0 = pk2(w4.x,w4.x), w1 = pk2(w4.y,w4.y);
            ull w2 = pk2(w4.z,w4.z), w3 = pk2(w4.w,w4.w);
            ull xs[8] = {xa.x,xa.y,xb.x,xb.y,xc.x,xc.y,xd.x,xd.y};
            #pragma unroll
            for (int p=0;p<8;p++){
                acc0[p] = fma2_(xs[p], w0, acc0[p]);
                acc1[p] = fma2_(xs[p], w1, acc1[p]);
                acc2[p] = fma2_(xs[p], w2, acc2[p]);
                acc3[p] = fma2_(xs[p], w3, acc3[p]);
            }
        }
        #pragma unroll
        for (int p=0;p<8;p++){
            float i0,i1,f0,f1,z0,z1,o0,o1;
            upk2(acc0[p],i0,i1); upk2(acc1[p],f0,f1);
            upk2(acc2[p],z0,z1); upk2(acc3[p],o0,o1);
            int s0 = tk0 + 2*p;
            *reinterpret_cast<float4*>(&g_gx[((size_t)(s0*Bm + b))*512 + oid*4])     = make_float4(i0,f0,z0,o0);
            *reinterpret_cast<float4*>(&g_gx[((size_t)((s0+1)*Bm + b))*512 + oid*4]) = make_float4(i1,f1,z1,o1);
        }
    }
}

// ---------------- sLSTM gate math ----------------
__device__ __forceinline__ float slstm_step(float i_r, float f_r, float z_r, float o_r,
                                            float& c, float& nn, float& m){
    float lsf = (f_r >= 0.f) ? (-__logf(1.f + __expf(-f_r)))
                             : (f_r - __logf(1.f + __expf(f_r)));
    float lfm = m + lsf;
    float mnew = fmaxf(i_r, lfm);
    float ig = __expf(i_r - mnew);
    float fg = __expf(lfm - mnew);
    float e2z = __expf(2.f*z_r);
    float tz = 1.f - 2.f/(e2z + 1.f);
    c  = fg*c  + ig*tz;
    nn = fg*nn + ig;
    m  = mnew;
    float so = 1.f/(1.f + __expf(-o_r));
    return so * c / nn;
}

// ================= sequential scan (warp-independent, syncwarp only) =================
// grid 256, 128 threads, 2 batches/CTA; double-buffered duplicated h-state
__global__ void __launch_bounds__(128,2) k_scan(const float* __restrict__ Rw,
                                                const float* __restrict__ bw,
                                                const float* __restrict__ gnw){
    __shared__ __align__(16) float hs[1024];  // [buf][slot][o*2]
    int tid = threadIdx.x;
    int n = tid >> 5, k = tid & 31;
    int b0 = blockIdx.x*2, b1 = b0 + 1;

    ull r01[32], r23[32];
    const float* rp = Rw + n*4096 + k;
    #pragma unroll
    for (int h = 0; h < 32; h++){
        r01[h] = pk2(rp[h*128],      rp[h*128 + 32]);
        r23[h] = pk2(rp[h*128 + 64], rp[h*128 + 96]);
    }
    float bias0 = bw[(n*4+0)*32+k], bias1 = bw[(n*4+1)*32+k];
    float bias2 = bw[(n*4+2)*32+k], bias3 = bw[(n*4+3)*32+k];
    float gw = gnw[n*32+k];

    int o = n*32 + k;
    *reinterpret_cast<ull*>(&hs[o*2])       = 0ull;
    *reinterpret_cast<ull*>(&hs[256 + o*2]) = 0ull;
    float ca=0.f, na=0.f, ma=0.f, cb=0.f, nb=0.f, mb=0.f;
    __syncwarp();

    const float4* pga = reinterpret_cast<const float4*>(&g_gx[(size_t)b0*512 + o*4]);
    const float4* pgb = reinterpret_cast<const float4*>(&g_gx[(size_t)b1*512 + o*4]);
    float4 ga = pga[0], gb = pgb[0];
    int cur = 0;

    for (int s = 0; s < Sm; s++){
        float4 gan = ga, gbn = gb;
        if (s < Sm-1){ gan = pga[(s+1)*65536]; gbn = pgb[(s+1)*65536]; }
        ull aa01=0, aa23=0, ab01=0, ab23=0;
        const ulonglong2* hpa = reinterpret_cast<const ulonglong2*>(&hs[cur*512 + n*64]);
        const ulonglong2* hpb = reinterpret_cast<const ulonglong2*>(&hs[cur*512 + 256 + n*64]);
        #pragma unroll
        for (int hh = 0; hh < 16; hh++){
            ulonglong2 ha = hpa[hh];
            ulonglong2 hb = hpb[hh];
            aa01 = fma2_(ha.x, r01[2*hh],   aa01);
            aa23 = fma2_(ha.x, r23[2*hh],   aa23);
            ab01 = fma2_(hb.x, r01[2*hh],   ab01);
            ab23 = fma2_(hb.x, r23[2*hh],   ab23);
            aa01 = fma2_(ha.y, r01[2*hh+1], aa01);
            aa23 = fma2_(ha.y, r23[2*hh+1], aa23);
            ab01 = fma2_(hb.y, r01[2*hh+1], ab01);
            ab23 = fma2_(hb.y, r23[2*hh+1], ab23);
        }
        float ria,rfa,rza,roa, rib,rfb,rzb,rob;
        upk2(aa01,ria,rfa); upk2(aa23,rza,roa);
        upk2(ab01,rib,rfb); upk2(ab23,rzb,rob);
        float hn_a = slstm_step(ria+ga.x+bias0, rfa+ga.y+bias1, rza+ga.z+bias2, roa+ga.w+bias3, ca,na,ma);
        float hn_b = slstm_step(rib+gb.x+bias0, rfb+gb.y+bias1, rzb+gb.z+bias2, rob+gb.w+bias3, cb,nb,mb);
        int nxt = cur ^ 1;
        *reinterpret_cast<ull*>(&hs[nxt*512 + o*2])       = pk2(hn_a, hn_a);
        *reinterpret_cast<ull*>(&hs[nxt*512 + 256 + o*2]) = pk2(hn_b, hn_b);
        __syncwarp();
        // GroupNorm (per warp == per head) + residual
        float sa = hn_a, qa = hn_a*hn_a, sb = hn_b, qb = hn_b*hn_b;
        #pragma unroll
        for (int off=16; off>0; off>>=1){
            sa += __shfl_xor_sync(0xffffffffu,sa,off);
            qa += __shfl_xor_sync(0xffffffffu,qa,off);
            sb += __shfl_xor_sync(0xffffffffu,sb,off);
            qb += __shfl_xor_sync(0xffffffffu,qb,off);
        }
        float mua = sa*(1.f/32.f);
        float inva = rsqrtf(qa*(1.f/32.f) - mua*mua + EPSm);
        float mub = sb*(1.f/32.f);
        float invb = rsqrtf(qb*(1.f/32.f) - mub*mub + EPSm);
        g_h[(size_t)(b0*64+s)*Dm + o] += (hn_a - mua)*inva*gw;
        g_h[(size_t)(b1*64+s)*Dm + o] += (hn_b - mub)*invb*gw;
        ga = gan; gb = gbn;
        cur = nxt;
    }
}

// ================= LN2 + up-proj + GeGLU -> g_v =================
// grid 128, 512 threads, 4 x 64-token tiles
#define UP_WST 260
#define UP_XST 68
#define UP_SMEM ((128*UP_WST + 128*UP_XST)*4)
__global__ void __launch_bounds__(512,1) k_up(const float* __restrict__ ln2w,
                                              const float* __restrict__ wup){
    extern __shared__ float sm[];
    float* Wup_s = sm;                    // [j][(d&127)*2 + (d>>7)] stride 260
    float* xns   = sm + 128*UP_WST;       // [j][t] stride 68
    int tid = threadIdx.x;
    for (int idx = tid; idx < 32768; idx += 512){
        int oo = idx >> 7, j = idx & 127;
        Wup_s[j*UP_WST + (oo&127)*2 + (oo>>7)] = wup[idx];
    }
    int wid = tid>>5, lane = tid&31;
    int dpair = tid & 63;                 // d2 = dpair*2
    int q = tid >> 6;                     // 0..7
    int tk0 = q*8;
    float4 lw = reinterpret_cast<const float4*>(ln2w)[lane];

    for (int it = 0; it < 4; it++){
        int blk = blockIdx.x*4 + it;
        __syncthreads();
        // LN: 64 tokens = 16 warps x 4
        #pragma unroll
        for (int pp = 0; pp < 4; pp++){
            int tok = pp*16 + wid;
            float4 v = reinterpret_cast<const float4*>(g_h + ((size_t)blk*64 + tok)*Dm)[lane];
            float s = v.x+v.y+v.z+v.w;
            float qq = v.x*v.x+v.y*v.y+v.z*v.z+v.w*v.w;
            #pragma unroll
            for (int of=16;of>0;of>>=1){ s += __shfl_xor_sync(0xffffffffu,s,of); qq += __shfl_xor_sync(0xffffffffu,qq,of); }
            float mu = s*(1.f/128.f);
            float inv = rsqrtf(qq*(1.f/128.f)-mu*mu+EPSm);
            xns[(lane*4+0)*UP_XST + tok] = (v.x-mu)*inv*lw.x;
            xns[(lane*4+1)*UP_XST + tok] = (v.y-mu)*inv*lw.y;
            xns[(lane*4+2)*UP_XST + tok] = (v.z-mu)*inv*lw.z;
            xns[(lane*4+3)*UP_XST + tok] = (v.w-mu)*inv*lw.w;
        }
        __syncthreads();
        ull aG0[4], aU0[4], aG1[4], aU1[4];
        #pragma unroll
        for (int p=0;p<4;p++){ aG0[p]=0; aU0[p]=0; aG1[p]=0; aU1[p]=0; }
        const float* wp  = Wup_s + dpair*4;
        const float* xp0 = xns + tk0;
        #pragma unroll 4
        for (int j = 0; j < 128; j++){
            float4 w = *reinterpret_cast<const float4*>(wp + j*UP_WST);
            ulonglong2 xA = *reinterpret_cast<const ulonglong2*>(xp0 + j*UP_XST);
            ulonglong2 xB = *reinterpret_cast<const ulonglong2*>(xp0 + j*UP_XST + 4);
            ull wg0 = pk2(w.x,w.x), wu0 = pk2(w.y,w.y);
            ull wg1 = pk2(w.z,w.z), wu1 = pk2(w.w,w.w);
            ull xs[4] = {xA.x, xA.y, xB.x, xB.y};
            #pragma unroll
            for (int p=0;p<4;p++){
                aG0[p] = fma2_(xs[p], wg0, aG0[p]);
                aU0[p] = fma2_(xs[p], wu0, aU0[p]);
                aG1[p] = fma2_(xs[p], wg1, aG1[p]);
                aU1[p] = fma2_(xs[p], wu1, aU1[p]);
            }
        }
        size_t vb0 = ((size_t)blk*128 + dpair*2)*64 + tk0;
        size_t vb1 = vb0 + 64;
        #pragma unroll
        for (int p=0;p<4;p++){
            float g0a,g0b,u0a,u0b,g1a,g1b,u1a,u1b;
            upk2(aG0[p],g0a,g0b); upk2(aU0[p],u0a,u0b);
            upk2(aG1[p],g1a,g1b); upk2(aU1[p],u1a,u1b);
            float v0a = 0.5f*g0a*(1.f+erff(g0a*0.70710678118f))*u0a;
            float v0b = 0.5f*g0b*(1.f+erff(g0b*0.70710678118f))*u0b;
            float v1a = 0.5f*g1a*(1.f+erff(g1a*0.70710678118f))*u1a;
            float v1b = 0.5f*g1b*(1.f+erff(g1b*0.70710678118f))*u1b;
            *reinterpret_cast<ull*>(&g_v[vb0 + 2*p]) = pk2(v0a,v0b);
            *reinterpret_cast<ull*>(&g_v[vb1 + 2*p]) = pk2(v1a,v1b);
        }
    }
}

// ================= down-proj + residual =================
// grid 256, 256 threads, 2 x 64-token tiles
#define DN_WST 132
#define DN_XST 68
#define DN_SMEM ((128*DN_WST + 128*DN_XST)*4)
__global__ void __launch_bounds__(256,2) k_down(const float* __restrict__ wdn){
    extern __shared__ float sm[];
    float* Wdn_s = sm;                    // [j][d] stride 132
    float* vs    = sm + 128*DN_WST;       // [j][t] stride 68
    int tid = threadIdx.x;
    for (int idx = tid; idx < 16384; idx += 256){
        int d = idx >> 7, j = idx & 127;
        Wdn_s[j*DN_WST + d] = wdn[idx];
    }
    int d4 = (tid & 31)*4;
    int q = tid >> 5;                     // 0..7
    int tk0 = q*8;

    for (int it = 0; it < 2; it++){
        int blk = blockIdx.x*2 + it;
        __syncthreads();
        for (int idx = tid; idx < 8192; idx += 256){
            int j = idx >> 6, tok = idx & 63;
            vs[j*DN_XST + tok] = g_v[((size_t)blk*128 + j)*64 + tok];
        }
        __syncthreads();
        ull aD0[4], aD1[4], aD2[4], aD3[4];
        #pragma unroll
        for (int p=0;p<4;p++){ aD0[p]=0; aD1[p]=0; aD2[p]=0; aD3[p]=0; }
        const float* wp  = Wdn_s + d4;
        const float* xp0 = vs + tk0;
        #pragma unroll 4
        for (int j = 0; j < 128; j++){
            float4 w = *reinterpret_cast<const float4*>(wp + j*DN_WST);
            ulonglong2 xA = *reinterpret_cast<const ulonglong2*>(xp0 + j*DN_XST);
            ulonglong2 xB = *reinterpret_cast<const ulonglong2*>(xp0 + j*DN_XST + 4);
            ull w0 = pk2(w.x,w.x), w1 = pk2(w.y,w.y);
            ull w2 = pk2(w.z,w.z), w3 = pk2(w.w,w.w);
            ull xs[4] = {xA.x, xA.y, xB.x, xB.y};
            #pragma unroll
            for (int p=0;p<4;p++){
                aD0[p] = fma2_(xs[p], w0, aD0[p]);
                aD1[p] = fma2_(xs[p], w1, aD1[p]);
                aD2[p] = fma2_(xs[p], w2, aD2[p]);
                aD3[p] = fma2_(xs[p], w3, aD3[p]);
            }
        }
        #pragma unroll
        for (int p=0;p<4;p++){
            float a0,b0,a1,b1,a2,b2,a3,b3;
            upk2(aD0[p],a0,b0); upk2(aD1[p],a1,b1);
            upk2(aD2[p],a2,b2); upk2(aD3[p],a3,b3);
            size_t t = (size_t)blk*64 + tk0 + 2*p;
            float4* hp0 = reinterpret_cast<float4*>(&g_h[t*Dm + d4]);
            float4* hp1 = reinterpret_cast<float4*>(&g_h[(t+1)*Dm + d4]);
            float4 h0 = *hp0, h1 = *hp1;
            h0.x += a0; h0.y += a1; h0.z += a2; h0.w += a3;
            h1.x += b0; h1.y += b1; h1.z += b2; h1.w += b3;
            *hp0 = h0; *hp1 = h1;
        }
        __syncthreads();
    }
}

// ---------------- final LN + vocab projection ----------------
__global__ void k_proj(const float* __restrict__ pw_ln, const float* __restrict__ pjw,
                       const float* __restrict__ pjb, float* __restrict__ out){
    int gt = blockIdx.x*8 + (threadIdx.x>>5);
    int lane = threadIdx.x & 31;
    float4 v = reinterpret_cast<const float4*>(g_h + (size_t)gt*Dm)[lane];
    float s = v.x+v.y+v.z+v.w;
    float q = v.x*v.x+v.y*v.y+v.z*v.z+v.w*v.w;
    #pragma unroll
    for (int o=16;o>0;o>>=1){ s += __shfl_xor_sync(0xffffffffu,s,o); q += __shfl_xor_sync(0xffffffffu,q,o); }
    float mu = s*(1.f/128.f);
    float inv = rsqrtf(q*(1.f/128.f) - mu*mu + EPSm);
    float4 wv = reinterpret_cast<const float4*>(pw_ln)[lane];
    float4 xv;
    xv.x=(v.x-mu)*inv*wv.x; xv.y=(v.y-mu)*inv*wv.y;
    xv.z=(v.z-mu)*inv*wv.z; xv.w=(v.w-mu)*inv*wv.w;
    float res = 0.f;
    #pragma unroll
    for (int vc = 0; vc < 9; vc++){
        float4 p = reinterpret_cast<const float4*>(pjw + vc*Dm)[lane];
        float sv = xv.x*p.x + xv.y*p.y + xv.z*p.z + xv.w*p.w;
        #pragma unroll
        for (int o=16;o>0;o>>=1) sv += __shfl_xor_sync(0xffffffffu,sv,o);
        if (lane == vc) res = sv;
    }
    if (lane < 9) out[gt*9 + lane] = res + pjb[lane];
}

// ---------------- launch ----------------
extern "C" void kernel_launch(void* const* d_in, const int* in_sizes, int n_in,
                              void* d_out, int out_size){
    const int*   x      = (const int*)  d_in[0];
    const float* emb    = (const float*)d_in[1];
    const float* ln1_w  = (const float*)d_in[2];
    const float* Wg     = (const float*)d_in[3];
    const float* R      = (const float*)d_in[4];
    const float* bias   = (const float*)d_in[5];
    const float* gn_w   = (const float*)d_in[6];
    const float* ln2_w  = (const float*)d_in[7];
    const float* ffu    = (const float*)d_in[8];
    const float* ffd    = (const float*)d_in[9];
    const float* post_w = (const float*)d_in[10];
    const float* pjw    = (const float*)d_in[11];
    const float* pjb    = (const float*)d_in[12];
    float* out = (float*)d_out;

    cudaFuncSetAttribute(k_gx,   cudaFuncAttributeMaxDynamicSharedMemorySize, GX_SMEM);
    cudaFuncSetAttribute(k_up,   cudaFuncAttributeMaxDynamicSharedMemorySize, UP_SMEM);
    cudaFuncSetAttribute(k_down, cudaFuncAttributeMaxDynamicSharedMemorySize, DN_SMEM);

    k_embed<<<4096,256>>>(x, emb);
    for (int bi = 0; bi < 2; bi++){
        k_gx  <<<128,512,GX_SMEM>>>(Wg + bi*16384, ln1_w + bi*Dm);
        k_scan<<<256,128>>>(R + bi*16384, bias + bi*512, gn_w + bi*Dm);
        k_up  <<<128,512,UP_SMEM>>>(ln2_w + bi*Dm, ffu + bi*32768);
        k_down<<<256,256,DN_SMEM>>>(ffd + bi*16384);
    }
    k_proj<<<4096,256>>>(post_w, pjw, pjb, out);
}

// round 9
// speedup vs baseline: 2.4215x; 1.2201x over previous
#include <cuda_runtime.h>
#include <cuda_bf16.h>
#include <math.h>
#include <stdint.h>
#include <cstdint>

#define Bm 512
#define Sm 64
#define Dm 128
#define EPSm 1e-5f
typedef unsigned long long ull;
typedef __nv_bfloat16 bf16;

// ---------------- scratch ----------------
__device__ float g_h[Bm*Sm*Dm];
__device__ float g_gx[(size_t)Sm*Bm*512];
__device__ __align__(16) bf16 g_xh[Bm*Sm*Dm], g_xl[Bm*Sm*Dm];
__device__ __align__(16) bf16 g_vh[Bm*Sm*Dm], g_vl[Bm*Sm*Dm];
__device__ __align__(16) bf16 g_wgh[2*512*32],  g_wgl[2*512*32];   // [blk][o=n*128+k*4+g][h]
__device__ __align__(16) bf16 g_wuh[2*256*128], g_wul[2*256*128];  // [blk][out][in]
__device__ __align__(16) bf16 g_wdh[2*128*128], g_wdl[2*128*128];  // [blk][out][in]

// ---------------- f32x2 helpers (scan) ----------------
__device__ __forceinline__ ull pk2(float a, float b){ ull r; asm("mov.b64 %0, {%1,%2};" : "=l"(r) : "f"(a), "f"(b)); return r; }
__device__ __forceinline__ void upk2(ull v, float &a, float &b){ asm("mov.b64 {%0,%1}, %2;" : "=f"(a), "=f"(b) : "l"(v)); }
__device__ __forceinline__ ull fma2_(ull a, ull b, ull c){ ull d; asm("fma.rn.f32x2 %0, %1, %2, %3;" : "=l"(d) : "l"(a), "l"(b), "l"(c)); return d; }

// ---------------- mma.sync helpers ----------------
__device__ __forceinline__ void mma_bf16(float* c, const uint32_t* a, const uint32_t* b){
    asm("mma.sync.aligned.m16n8k16.row.col.f32.bf16.bf16.f32 "
        "{%0,%1,%2,%3}, {%4,%5,%6,%7}, {%8,%9}, {%0,%1,%2,%3};"
        : "+f"(c[0]), "+f"(c[1]), "+f"(c[2]), "+f"(c[3])
        : "r"(a[0]), "r"(a[1]), "r"(a[2]), "r"(a[3]), "r"(b[0]), "r"(b[1]));
}
// A frag (m16k16, row-major) from smem at (r0,k0), stride S elements
__device__ __forceinline__ void lda(uint32_t* a, const bf16* base, int S, int gr, int gc){
    a[0] = *reinterpret_cast<const uint32_t*>(base + gr*S + gc);
    a[1] = *reinterpret_cast<const uint32_t*>(base + (gr+8)*S + gc);
    a[2] = *reinterpret_cast<const uint32_t*>(base + gr*S + gc + 8);
    a[3] = *reinterpret_cast<const uint32_t*>(base + (gr+8)*S + gc + 8);
}
// B frag (k16n8) from W[n][k] row-major at (n0,k0), stride S
__device__ __forceinline__ void ldb(uint32_t* b, const bf16* base, int S, int gr, int gc){
    b[0] = *reinterpret_cast<const uint32_t*>(base + gr*S + gc);
    b[1] = *reinterpret_cast<const uint32_t*>(base + gr*S + gc + 8);
}
// 2-term split: Ah*Bh + Ah*Bl + Al*Bh
__device__ __forceinline__ void mma3(float* c, const uint32_t* ah, const uint32_t* al,
                                     const uint32_t* bh, const uint32_t* bl){
    mma_bf16(c, ah, bh);
    mma_bf16(c, ah, bl);
    mma_bf16(c, al, bh);
}

__device__ __forceinline__ void bsplit(float x, bf16& h, bf16& l){
    h = __float2bfloat16(x);
    l = __float2bfloat16(x - __bfloat162float(h));
}
__device__ __forceinline__ float gelu_(float g){
    return 0.5f*g*(1.f + erff(g*0.70710678118f));
}

// ---------------- embedding ----------------
__global__ void k_embed(const int* __restrict__ x, const float* __restrict__ emb){
    int i = blockIdx.x*blockDim.x + threadIdx.x;
    int t = i >> 5, d4 = i & 31;
    int v = x[t];
    reinterpret_cast<float4*>(g_h)[t*32 + d4] =
        reinterpret_cast<const float4*>(emb)[v*32 + d4];
}

// ---------------- weight prep ----------------
__global__ void k_prep(const float* __restrict__ wg, const float* __restrict__ wu,
                       const float* __restrict__ wd){
    int id = blockIdx.x*256 + threadIdx.x;   // 131072 total
    if (id < 32768){
        int blk = id >> 14, rem = id & 16383;
        int o = rem >> 5, h = rem & 31;
        int n = o >> 7, r = o & 127, kk = r >> 2, g = r & 3;
        float val = wg[(((blk*4 + g)*4 + n)*32 + kk)*32 + h];
        bf16 hi, lo; bsplit(val, hi, lo);
        g_wgh[id] = hi; g_wgl[id] = lo;
    } else if (id < 98304){
        int t = id - 32768;
        bf16 hi, lo; bsplit(wu[t], hi, lo);
        g_wuh[t] = hi; g_wul[t] = lo;
    } else {
        int t = id - 98304;
        bf16 hi, lo; bsplit(wd[t], hi, lo);
        g_wdh[t] = hi; g_wdl[t] = lo;
    }
}

// ---------------- layernorm h -> split bf16 ----------------
__global__ void k_lnb(const float* __restrict__ w){
    int gt = blockIdx.x*8 + (threadIdx.x>>5);
    int lane = threadIdx.x & 31;
    float4 v = reinterpret_cast<const float4*>(g_h + (size_t)gt*Dm)[lane];
    float s = v.x+v.y+v.z+v.w;
    float q = v.x*v.x+v.y*v.y+v.z*v.z+v.w*v.w;
    #pragma unroll
    for (int o=16;o>0;o>>=1){ s += __shfl_xor_sync(0xffffffffu,s,o); q += __shfl_xor_sync(0xffffffffu,q,o); }
    float mu = s*(1.f/128.f);
    float inv = rsqrtf(q*(1.f/128.f) - mu*mu + EPSm);
    float4 wv = reinterpret_cast<const float4*>(w)[lane];
    float xv0 = (v.x-mu)*inv*wv.x;
    float xv1 = (v.y-mu)*inv*wv.y;
    float xv2 = (v.z-mu)*inv*wv.z;
    float xv3 = (v.w-mu)*inv*wv.w;
    bf16 h0,l0,h1,l1,h2,l2,h3,l3;
    bsplit(xv0,h0,l0); bsplit(xv1,h1,l1); bsplit(xv2,h2,l2); bsplit(xv3,h3,l3);
    size_t base = (size_t)gt*Dm + lane*4;
    __nv_bfloat162 t0; t0.x=h0; t0.y=h1;
    __nv_bfloat162 t1; t1.x=h2; t1.y=h3;
    __nv_bfloat162 t2; t2.x=l0; t2.y=l1;
    __nv_bfloat162 t3; t3.x=l2; t3.y=l3;
    *reinterpret_cast<__nv_bfloat162*>(&g_xh[base])   = t0;
    *reinterpret_cast<__nv_bfloat162*>(&g_xh[base+2]) = t1;
    *reinterpret_cast<__nv_bfloat162*>(&g_xl[base])   = t2;
    *reinterpret_cast<__nv_bfloat162*>(&g_xl[base+2]) = t3;
}

// ================= gate GEMM (block-diagonal, K=32 per head) =================
// grid 128, 256 thr, 2 m-tiles of 128 tokens
// smem el: Ah 0, Al 17408 (128x136), Wh 34816 (512x40), Wl 55296; total 75776 el
#define GXS_SMEM (75776*2)
__global__ void __launch_bounds__(256,1) k_mma_gx(int blk){
    extern __shared__ bf16 smg[];
    bf16 *Ah = smg, *Al = smg + 17408, *Wh = smg + 34816, *Wl = smg + 55296;
    int tid = threadIdx.x, w = tid>>5, lane = tid&31;
    int gr = lane>>2, gc = (lane&3)*2;
    const bf16* wh = g_wgh + blk*16384;
    const bf16* wl = g_wgl + blk*16384;
    for (int i = tid; i < 2048; i += 256){
        int r = i>>2, c8 = (i&3)*8;
        *reinterpret_cast<uint4*>(Wh + r*40 + c8) = *reinterpret_cast<const uint4*>(wh + r*32 + c8);
        *reinterpret_cast<uint4*>(Wl + r*40 + c8) = *reinterpret_cast<const uint4*>(wl + r*32 + c8);
    }
    for (int mt = 0; mt < 2; mt++){
        int t0 = (blockIdx.x*2 + mt)*128;
        __syncthreads();
        for (int i = tid; i < 2048; i += 256){
            int r = i>>4, c8 = (i&15)*8;
            *reinterpret_cast<uint4*>(Ah + r*136 + c8) = *reinterpret_cast<const uint4*>(g_xh + (size_t)(t0+r)*128 + c8);
            *reinterpret_cast<uint4*>(Al + r*136 + c8) = *reinterpret_cast<const uint4*>(g_xl + (size_t)(t0+r)*128 + c8);
        }
        __syncthreads();
        int m0 = (w&3)*32;
        #pragma unroll 1
        for (int it = 0; it < 4; it++){
            int ng = (w>>2) + it*2;        // n64 group 0..7
            int head = ng >> 1;
            int nb = ng*64;                // global out base
            float acc[2][8][4];
            #pragma unroll
            for (int ms=0;ms<2;ms++)
                #pragma unroll
                for (int nt=0;nt<8;nt++)
                    #pragma unroll
                    for (int i=0;i<4;i++) acc[ms][nt][i]=0.f;
            #pragma unroll
            for (int kc = 0; kc < 2; kc++){
                int k0 = head*32 + kc*16;
                uint32_t ah0[4], ah1[4], al0[4], al1[4];
                lda(ah0, Ah + (m0)*136 + k0, 136, gr, gc);
                lda(ah1, Ah + (m0+16)*136 + k0, 136, gr, gc);
                lda(al0, Al + (m0)*136 + k0, 136, gr, gc);
                lda(al1, Al + (m0+16)*136 + k0, 136, gr, gc);
                #pragma unroll
                for (int nt = 0; nt < 8; nt++){
                    int nr = nb + nt*8;
                    uint32_t bh[2], bl[2];
                    ldb(bh, Wh + nr*40 + kc*16, 40, gr, gc);
                    ldb(bl, Wl + nr*40 + kc*16, 40, gr, gc);
                    mma3(acc[0][nt], ah0, al0, bh, bl);
                    mma3(acc[1][nt], ah1, al1, bh, bl);
                }
            }
            #pragma unroll
            for (int ms=0;ms<2;ms++){
                int tA = t0 + m0 + ms*16 + gr;
                int tB = tA + 8;
                int bA = tA>>6, sA = tA&63;
                int bB = tB>>6, sB = tB&63;
                float* dA = &g_gx[((size_t)(sA*Bm + bA))*512];
                float* dB = &g_gx[((size_t)(sB*Bm + bB))*512];
                #pragma unroll
                for (int nt=0;nt<8;nt++){
                    int col = nb + nt*8 + gc;
                    *reinterpret_cast<float2*>(dA + col) = make_float2(acc[ms][nt][0], acc[ms][nt][1]);
                    *reinterpret_cast<float2*>(dB + col) = make_float2(acc[ms][nt][2], acc[ms][nt][3]);
                }
            }
        }
    }
}

// ================= FF up + GeGLU -> split v =================
// smem el: Ah 0, Al 17408, Wh 34816 (256x136), Wl 69632; total 104448 el
#define UPS_SMEM (104448*2)
__global__ void __launch_bounds__(256,1) k_mma_up(int blk){
    extern __shared__ bf16 smu[];
    bf16 *Ah = smu, *Al = smu + 17408, *Wh = smu + 34816, *Wl = smu + 69632;
    int tid = threadIdx.x, w = tid>>5, lane = tid&31;
    int gr = lane>>2, gc = (lane&3)*2;
    const bf16* wh = g_wuh + blk*32768;
    const bf16* wl = g_wul + blk*32768;
    for (int i = tid; i < 4096; i += 256){
        int r = i>>4, c8 = (i&15)*8;
        *reinterpret_cast<uint4*>(Wh + r*136 + c8) = *reinterpret_cast<const uint4*>(wh + r*128 + c8);
        *reinterpret_cast<uint4*>(Wl + r*136 + c8) = *reinterpret_cast<const uint4*>(wl + r*128 + c8);
    }
    for (int mt = 0; mt < 2; mt++){
        int t0 = (blockIdx.x*2 + mt)*128;
        __syncthreads();
        for (int i = tid; i < 2048; i += 256){
            int r = i>>4, c8 = (i&15)*8;
            *reinterpret_cast<uint4*>(Ah + r*136 + c8) = *reinterpret_cast<const uint4*>(g_xh + (size_t)(t0+r)*128 + c8);
            *reinterpret_cast<uint4*>(Al + r*136 + c8) = *reinterpret_cast<const uint4*>(g_xl + (size_t)(t0+r)*128 + c8);
        }
        __syncthreads();
        int m0 = (w&3)*32;
        #pragma unroll 1
        for (int it = 0; it < 2; it++){
            int nb = ((w>>2) + it*2)*32;   // gate col base 0..127
            float ga[2][4][4], ua[2][4][4];
            #pragma unroll
            for (int ms=0;ms<2;ms++)
                #pragma unroll
                for (int nt=0;nt<4;nt++)
                    #pragma unroll
                    for (int i=0;i<4;i++){ ga[ms][nt][i]=0.f; ua[ms][nt][i]=0.f; }
            #pragma unroll
            for (int kc = 0; kc < 8; kc++){
                int k0 = kc*16;
                uint32_t ah0[4], ah1[4], al0[4], al1[4];
                lda(ah0, Ah + (m0)*136 + k0, 136, gr, gc);
                lda(ah1, Ah + (m0+16)*136 + k0, 136, gr, gc);
                lda(al0, Al + (m0)*136 + k0, 136, gr, gc);
                lda(al1, Al + (m0+16)*136 + k0, 136, gr, gc);
                #pragma unroll
                for (int nt = 0; nt < 4; nt++){
                    int nr = nb + nt*8;
                    uint32_t bgh[2], bgl[2], buh[2], bul[2];
                    ldb(bgh, Wh + nr*136 + k0, 136, gr, gc);
                    ldb(bgl, Wl + nr*136 + k0, 136, gr, gc);
                    ldb(buh, Wh + (128+nr)*136 + k0, 136, gr, gc);
                    ldb(bul, Wl + (128+nr)*136 + k0, 136, gr, gc);
                    mma3(ga[0][nt], ah0, al0, bgh, bgl);
                    mma3(ga[1][nt], ah1, al1, bgh, bgl);
                    mma3(ua[0][nt], ah0, al0, buh, bul);
                    mma3(ua[1][nt], ah1, al1, buh, bul);
                }
            }
            #pragma unroll
            for (int ms=0;ms<2;ms++){
                size_t rA = (size_t)(t0 + m0 + ms*16 + gr)*128;
                size_t rB = rA + 8*128;
                #pragma unroll
                for (int nt=0;nt<4;nt++){
                    int col = nb + nt*8 + gc;
                    float v0 = gelu_(ga[ms][nt][0])*ua[ms][nt][0];
                    float v1 = gelu_(ga[ms][nt][1])*ua[ms][nt][1];
                    float v2 = gelu_(ga[ms][nt][2])*ua[ms][nt][2];
                    float v3 = gelu_(ga[ms][nt][3])*ua[ms][nt][3];
                    bf16 h0,l0,h1,l1,h2,l2,h3,l3;
                    bsplit(v0,h0,l0); bsplit(v1,h1,l1); bsplit(v2,h2,l2); bsplit(v3,h3,l3);
                    __nv_bfloat162 p0; p0.x=h0; p0.y=h1;
                    __nv_bfloat162 p1; p1.x=h2; p1.y=h3;
                    __nv_bfloat162 q0; q0.x=l0; q0.y=l1;
                    __nv_bfloat162 q1; q1.x=l2; q1.y=l3;
                    *reinterpret_cast<__nv_bfloat162*>(&g_vh[rA + col]) = p0;
                    *reinterpret_cast<__nv_bfloat162*>(&g_vh[rB + col]) = p1;
                    *reinterpret_cast<__nv_bfloat162*>(&g_vl[rA + col]) = q0;
                    *reinterpret_cast<__nv_bfloat162*>(&g_vl[rB + col]) = q1;
                }
            }
        }
    }
}

// ================= FF down + residual =================
// smem el: Ah 0, Al 17408, Wh 34816 (128x136), Wl 52224; total 69632 el
#define DNS_SMEM (69632*2)
__global__ void __launch_bounds__(256,1) k_mma_down(int blk){
    extern __shared__ bf16 smd[];
    bf16 *Ah = smd, *Al = smd + 17408, *Wh = smd + 34816, *Wl = smd + 52224;
    int tid = threadIdx.x, w = tid>>5, lane = tid&31;
    int gr = lane>>2, gc = (lane&3)*2;
    const bf16* wh = g_wdh + blk*16384;
    const bf16* wl = g_wdl + blk*16384;
    for (int i = tid; i < 2048; i += 256){
        int r = i>>4, c8 = (i&15)*8;
        *reinterpret_cast<uint4*>(Wh + r*136 + c8) = *reinterpret_cast<const uint4*>(wh + r*128 + c8);
        *reinterpret_cast<uint4*>(Wl + r*136 + c8) = *reinterpret_cast<const uint4*>(wl + r*128 + c8);
    }
    for (int mt = 0; mt < 2; mt++){
        int t0 = (blockIdx.x*2 + mt)*128;
        __syncthreads();
        for (int i = tid; i < 2048; i += 256){
            int r = i>>4, c8 = (i&15)*8;
            *reinterpret_cast<uint4*>(Ah + r*136 + c8) = *reinterpret_cast<const uint4*>(g_vh + (size_t)(t0+r)*128 + c8);
            *reinterpret_cast<uint4*>(Al + r*136 + c8) = *reinterpret_cast<const uint4*>(g_vl + (size_t)(t0+r)*128 + c8);
        }
        __syncthreads();
        int m0 = (w&3)*32;
        int nb = (w>>2)*64;
        float acc[2][8][4];
        #pragma unroll
        for (int ms=0;ms<2;ms++)
            #pragma unroll
            for (int nt=0;nt<8;nt++)
                #pragma unroll
                for (int i=0;i<4;i++) acc[ms][nt][i]=0.f;
        #pragma unroll
        for (int kc = 0; kc < 8; kc++){
            int k0 = kc*16;
            uint32_t ah0[4], ah1[4], al0[4], al1[4];
            lda(ah0, Ah + (m0)*136 + k0, 136, gr, gc);
            lda(ah1, Ah + (m0+16)*136 + k0, 136, gr, gc);
            lda(al0, Al + (m0)*136 + k0, 136, gr, gc);
            lda(al1, Al + (m0+16)*136 + k0, 136, gr, gc);
            #pragma unroll
            for (int nt = 0; nt < 8; nt++){
                int nr = nb + nt*8;
                uint32_t bh[2], bl[2];
                ldb(bh, Wh + nr*136 + k0, 136, gr, gc);
                ldb(bl, Wl + nr*136 + k0, 136, gr, gc);
                mma3(acc[0][nt], ah0, al0, bh, bl);
                mma3(acc[1][nt], ah1, al1, bh, bl);
            }
        }
        #pragma unroll
        for (int ms=0;ms<2;ms++){
            size_t rA = (size_t)(t0 + m0 + ms*16 + gr)*128;
            size_t rB = rA + 8*128;
            #pragma unroll
            for (int nt=0;nt<8;nt++){
                int col = nb + nt*8 + gc;
                float2* pA = reinterpret_cast<float2*>(&g_h[rA + col]);
                float2* pB = reinterpret_cast<float2*>(&g_h[rB + col]);
                float2 hA = *pA, hB = *pB;
                hA.x += acc[ms][nt][0]; hA.y += acc[ms][nt][1];
                hB.x += acc[ms][nt][2]; hB.y += acc[ms][nt][3];
                *pA = hA; *pB = hB;
            }
        }
    }
}

// ---------------- sLSTM gate math ----------------
__device__ __forceinline__ float slstm_step(float i_r, float f_r, float z_r, float o_r,
                                            float& c, float& nn, float& m){
    float lsf = (f_r >= 0.f) ? (-__logf(1.f + __expf(-f_r)))
                             : (f_r - __logf(1.f + __expf(f_r)));
    float lfm = m + lsf;
    float mnew = fmaxf(i_r, lfm);
    float ig = __expf(i_r - mnew);
    float fg = __expf(lfm - mnew);
    float e2z = __expf(2.f*z_r);
    float tz = 1.f - 2.f/(e2z + 1.f);
    c  = fg*c  + ig*tz;
    nn = fg*nn + ig;
    m  = mnew;
    float so = 1.f/(1.f + __expf(-o_r));
    return so * c / nn;
}

// ================= sequential scan =================
__global__ void __launch_bounds__(128,2) k_scan(const float* __restrict__ Rw,
                                                const float* __restrict__ bw,
                                                const float* __restrict__ gnw){
    __shared__ __align__(16) float hs[1024];
    int tid = threadIdx.x;
    int n = tid >> 5, k = tid & 31;
    int b0 = blockIdx.x*2, b1 = b0 + 1;

    ull r01[32], r23[32];
    const float* rp = Rw + n*4096 + k;
    #pragma unroll
    for (int h = 0; h < 32; h++){
        r01[h] = pk2(rp[h*128],      rp[h*128 + 32]);
        r23[h] = pk2(rp[h*128 + 64], rp[h*128 + 96]);
    }
    float bias0 = bw[(n*4+0)*32+k], bias1 = bw[(n*4+1)*32+k];
    float bias2 = bw[(n*4+2)*32+k], bias3 = bw[(n*4+3)*32+k];
    float gw = gnw[n*32+k];

    int o = n*32 + k;
    *reinterpret_cast<ull*>(&hs[o*2])       = 0ull;
    *reinterpret_cast<ull*>(&hs[256 + o*2]) = 0ull;
    float ca=0.f, na=0.f, ma=0.f, cb=0.f, nb=0.f, mb=0.f;
    __syncwarp();

    const float4* pga = reinterpret_cast<const float4*>(&g_gx[(size_t)b0*512 + o*4]);
    const float4* pgb = reinterpret_cast<const float4*>(&g_gx[(size_t)b1*512 + o*4]);
    float4 ga = pga[0], gb = pgb[0];
    int cur = 0;

    for (int s = 0; s < Sm; s++){
        float4 gan = ga, gbn = gb;
        if (s < Sm-1){ gan = pga[(s+1)*65536]; gbn = pgb[(s+1)*65536]; }
        ull aa01=0, aa23=0, ab01=0, ab23=0;
        const ulonglong2* hpa = reinterpret_cast<const ulonglong2*>(&hs[cur*512 + n*64]);
        const ulonglong2* hpb = reinterpret_cast<const ulonglong2*>(&hs[cur*512 + 256 + n*64]);
        #pragma unroll
        for (int hh = 0; hh < 16; hh++){
            ulonglong2 ha = hpa[hh];
            ulonglong2 hb = hpb[hh];
            aa01 = fma2_(ha.x, r01[2*hh],   aa01);
            aa23 = fma2_(ha.x, r23[2*hh],   aa23);
            ab01 = fma2_(hb.x, r01[2*hh],   ab01);
            ab23 = fma2_(hb.x, r23[2*hh],   ab23);
            aa01 = fma2_(ha.y, r01[2*hh+1], aa01);
            aa23 = fma2_(ha.y, r23[2*hh+1], aa23);
            ab01 = fma2_(hb.y, r01[2*hh+1], ab01);
            ab23 = fma2_(hb.y, r23[2*hh+1], ab23);
        }
        float ria,rfa,rza,roa, rib,rfb,rzb,rob;
        upk2(aa01,ria,rfa); upk2(aa23,rza,roa);
        upk2(ab01,rib,rfb); upk2(ab23,rzb,rob);
        float hn_a = slstm_step(ria+ga.x+bias0, rfa+ga.y+bias1, rza+ga.z+bias2, roa+ga.w+bias3, ca,na,ma);
        float hn_b = slstm_step(rib+gb.x+bias0, rfb+gb.y+bias1, rzb+gb.z+bias2, rob+gb.w+bias3, cb,nb,mb);
        int nxt = cur ^ 1;
        *reinterpret_cast<ull*>(&hs[nxt*512 + o*2])       = pk2(hn_a, hn_a);
        *reinterpret_cast<ull*>(&hs[nxt*512 + 256 + o*2]) = pk2(hn_b, hn_b);
        __syncwarp();
        float sa = hn_a, qa = hn_a*hn_a, sb2 = hn_b, qb = hn_b*hn_b;
        #pragma unroll
        for (int off=16; off>0; off>>=1){
            sa  += __shfl_xor_sync(0xffffffffu,sa,off);
            qa  += __shfl_xor_sync(0xffffffffu,qa,off);
            sb2 += __shfl_xor_sync(0xffffffffu,sb2,off);
            qb  += __shfl_xor_sync(0xffffffffu,qb,off);
        }
        float mua = sa*(1.f/32.f);
        float inva = rsqrtf(qa*(1.f/32.f) - mua*mua + EPSm);
        float mub = sb2*(1.f/32.f);
        float invb = rsqrtf(qb*(1.f/32.f) - mub*mub + EPSm);
        g_h[(size_t)(b0*64+s)*Dm + o] += (hn_a - mua)*inva*gw;
        g_h[(size_t)(b1*64+s)*Dm + o] += (hn_b - mub)*invb*gw;
        ga = gan; gb = gbn;
        cur = nxt;
    }
}

// ---------------- final LN + vocab projection ----------------
__global__ void k_proj(const float* __restrict__ pw_ln, const float* __restrict__ pjw,
                       const float* __restrict__ pjb, float* __restrict__ out){
    int gt = blockIdx.x*8 + (threadIdx.x>>5);
    int lane = threadIdx.x & 31;
    float4 v = reinterpret_cast<const float4*>(g_h + (size_t)gt*Dm)[lane];
    float s = v.x+v.y+v.z+v.w;
    float q = v.x*v.x+v.y*v.y+v.z*v.z+v.w*v.w;
    #pragma unroll
    for (int o=16;o>0;o>>=1){ s += __shfl_xor_sync(0xffffffffu,s,o); q += __shfl_xor_sync(0xffffffffu,q,o); }
    float mu = s*(1.f/128.f);
    float inv = rsqrtf(q*(1.f/128.f) - mu*mu + EPSm);
    float4 wv = reinterpret_cast<const float4*>(pw_ln)[lane];
    float4 xv;
    xv.x=(v.x-mu)*inv*wv.x; xv.y=(v.y-mu)*inv*wv.y;
    xv.z=(v.z-mu)*inv*wv.z; xv.w=(v.w-mu)*inv*wv.w;
    float res = 0.f;
    #pragma unroll
    for (int vc = 0; vc < 9; vc++){
        float4 p = reinterpret_cast<const float4*>(pjw + vc*Dm)[lane];
        float sv = xv.x*p.x + xv.y*p.y + xv.z*p.z + xv.w*p.w;
        #pragma unroll
        for (int o=16;o>0;o>>=1) sv += __shfl_xor_sync(0xffffffffu,sv,o);
        if (lane == vc) res = sv;
    }
    if (lane < 9) out[gt*9 + lane] = res + pjb[lane];
}

// ---------------- launch ----------------
extern "C" void kernel_launch(void* const* d_in, const int* in_sizes, int n_in,
                              void* d_out, int out_size){
    const int*   x      = (const int*)  d_in[0];
    const float* emb    = (const float*)d_in[1];
    const float* ln1_w  = (const float*)d_in[2];
    const float* Wg     = (const float*)d_in[3];
    const float* R      = (const float*)d_in[4];
    const float* bias   = (const float*)d_in[5];
    const float* gn_w   = (const float*)d_in[6];
    const float* ln2_w  = (const float*)d_in[7];
    const float* ffu    = (const float*)d_in[8];
    const float* ffd    = (const float*)d_in[9];
    const float* post_w = (const float*)d_in[10];
    const float* pjw    = (const float*)d_in[11];
    const float* pjb    = (const float*)d_in[12];
    float* out = (float*)d_out;

    cudaFuncSetAttribute(k_mma_gx,   cudaFuncAttributeMaxDynamicSharedMemorySize, GXS_SMEM);
    cudaFuncSetAttribute(k_mma_up,   cudaFuncAttributeMaxDynamicSharedMemorySize, UPS_SMEM);
    cudaFuncSetAttribute(k_mma_down, cudaFuncAttributeMaxDynamicSharedMemorySize, DNS_SMEM);

    k_embed<<<4096,256>>>(x, emb);
    k_prep <<<512,256>>>(Wg, ffu, ffd);
    for (int bi = 0; bi < 2; bi++){
        k_lnb     <<<4096,256>>>(ln1_w + bi*Dm);
        k_mma_gx  <<<128,256,GXS_SMEM>>>(bi);
        k_scan    <<<256,128>>>(R + bi*16384, bias + bi*512, gn_w + bi*Dm);
        k_lnb     <<<4096,256>>>(ln2_w + bi*Dm);
        k_mma_up  <<<128,256,UPS_SMEM>>>(bi);
        k_mma_down<<<128,256,DNS_SMEM>>>(bi);
    }
    k_proj<<<4096,256>>>(post_w, pjw, pjb, out);
}

// round 10
// speedup vs baseline: 2.5828x; 1.0666x over previous
#include <cuda_runtime.h>
#include <cuda_bf16.h>
#include <math.h>
#include <stdint.h>
#include <cstdint>

#define Bm 512
#define Sm 64
#define Dm 128
#define EPSm 1e-5f
typedef unsigned long long ull;
typedef __nv_bfloat16 bf16;

// ---------------- scratch ----------------
__device__ float g_h[Bm*Sm*Dm];
__device__ float g_gx[(size_t)Sm*Bm*512];
__device__ __align__(16) bf16 g_vh[Bm*Sm*Dm], g_vl[Bm*Sm*Dm];
__device__ __align__(16) bf16 g_wgh[2*512*32],  g_wgl[2*512*32];   // [blk][o=n*128+k*4+g][h]
__device__ __align__(16) bf16 g_wuh[2*256*128], g_wul[2*256*128];  // [blk][out][in]
__device__ __align__(16) bf16 g_wdh[2*128*128], g_wdl[2*128*128];  // [blk][out][in]

// ---------------- f32x2 helpers (scan) ----------------
__device__ __forceinline__ ull pk2(float a, float b){ ull r; asm("mov.b64 %0, {%1,%2};" : "=l"(r) : "f"(a), "f"(b)); return r; }
__device__ __forceinline__ void upk2(ull v, float &a, float &b){ asm("mov.b64 {%0,%1}, %2;" : "=f"(a), "=f"(b) : "l"(v)); }
__device__ __forceinline__ ull fma2_(ull a, ull b, ull c){ ull d; asm("fma.rn.f32x2 %0, %1, %2, %3;" : "=l"(d) : "l"(a), "l"(b), "l"(c)); return d; }

// ---------------- mma helpers ----------------
__device__ __forceinline__ uint32_t s2u(const void* p){ return (uint32_t)__cvta_generic_to_shared(p); }
__device__ __forceinline__ void mma_bf16(float* c, const uint32_t* a, const uint32_t* b){
    asm("mma.sync.aligned.m16n8k16.row.col.f32.bf16.bf16.f32 "
        "{%0,%1,%2,%3}, {%4,%5,%6,%7}, {%8,%9}, {%0,%1,%2,%3};"
        : "+f"(c[0]), "+f"(c[1]), "+f"(c[2]), "+f"(c[3])
        : "r"(a[0]), "r"(a[1]), "r"(a[2]), "r"(a[3]), "r"(b[0]), "r"(b[1]));
}
__device__ __forceinline__ void ldsm4(uint32_t* r, uint32_t addr){
    asm volatile("ldmatrix.sync.aligned.m8n8.x4.shared.b16 {%0,%1,%2,%3}, [%4];"
        : "=r"(r[0]),"=r"(r[1]),"=r"(r[2]),"=r"(r[3]) : "r"(addr));
}
__device__ __forceinline__ void ldsm2(uint32_t* r, uint32_t addr){
    asm volatile("ldmatrix.sync.aligned.m8n8.x2.shared.b16 {%0,%1}, [%2];"
        : "=r"(r[0]),"=r"(r[1]) : "r"(addr));
}
__device__ __forceinline__ void mma3(float* c, const uint32_t* ah, const uint32_t* al,
                                     const uint32_t* bh, const uint32_t* bl){
    mma_bf16(c, ah, bh);
    mma_bf16(c, ah, bl);
    mma_bf16(c, al, bh);
}
__device__ __forceinline__ void bsplit(float x, bf16& h, bf16& l){
    h = __float2bfloat16(x);
    l = __float2bfloat16(x - __bfloat162float(h));
}
__device__ __forceinline__ float gelu_(float g){
    return 0.5f*g*(1.f + erff(g*0.70710678118f));
}

// LN one token (warp-collective) -> split bf16 into padded smem row (stride 136)
__device__ __forceinline__ void ln_row(const float* __restrict__ hrow, float4 lw, int lane,
                                       bf16* Ah, bf16* Al, int tok){
    float4 v = reinterpret_cast<const float4*>(hrow)[lane];
    float s = v.x+v.y+v.z+v.w;
    float q = v.x*v.x+v.y*v.y+v.z*v.z+v.w*v.w;
    #pragma unroll
    for (int o=16;o>0;o>>=1){ s += __shfl_xor_sync(0xffffffffu,s,o); q += __shfl_xor_sync(0xffffffffu,q,o); }
    float mu = s*(1.f/128.f);
    float inv = rsqrtf(q*(1.f/128.f) - mu*mu + EPSm);
    float x0=(v.x-mu)*inv*lw.x, x1=(v.y-mu)*inv*lw.y;
    float x2=(v.z-mu)*inv*lw.z, x3=(v.w-mu)*inv*lw.w;
    bf16 h0,l0,h1,l1,h2,l2,h3,l3;
    bsplit(x0,h0,l0); bsplit(x1,h1,l1); bsplit(x2,h2,l2); bsplit(x3,h3,l3);
    int base = tok*136 + lane*4;
    __nv_bfloat162 p0; p0.x=h0; p0.y=h1;
    __nv_bfloat162 p1; p1.x=h2; p1.y=h3;
    __nv_bfloat162 q0; q0.x=l0; q0.y=l1;
    __nv_bfloat162 q1; q1.x=l2; q1.y=l3;
    *reinterpret_cast<__nv_bfloat162*>(Ah+base)   = p0;
    *reinterpret_cast<__nv_bfloat162*>(Ah+base+2) = p1;
    *reinterpret_cast<__nv_bfloat162*>(Al+base)   = q0;
    *reinterpret_cast<__nv_bfloat162*>(Al+base+2) = q1;
}

// ---------------- embedding ----------------
__global__ void k_embed(const int* __restrict__ x, const float* __restrict__ emb){
    int i = blockIdx.x*blockDim.x + threadIdx.x;
    int t = i >> 5, d4 = i & 31;
    int v = x[t];
    reinterpret_cast<float4*>(g_h)[t*32 + d4] =
        reinterpret_cast<const float4*>(emb)[v*32 + d4];
}

// ---------------- weight prep ----------------
__global__ void k_prep(const float* __restrict__ wg, const float* __restrict__ wu,
                       const float* __restrict__ wd){
    int id = blockIdx.x*256 + threadIdx.x;   // 131072 total
    if (id < 32768){
        int blk = id >> 14, rem = id & 16383;
        int o = rem >> 5, h = rem & 31;
        int n = o >> 7, r = o & 127, kk = r >> 2, g = r & 3;
        float val = wg[(((blk*4 + g)*4 + n)*32 + kk)*32 + h];
        bf16 hi, lo; bsplit(val, hi, lo);
        g_wgh[id] = hi; g_wgl[id] = lo;
    } else if (id < 98304){
        int t = id - 32768;
        bf16 hi, lo; bsplit(wu[t], hi, lo);
        g_wuh[t] = hi; g_wul[t] = lo;
    } else {
        int t = id - 98304;
        bf16 hi, lo; bsplit(wd[t], hi, lo);
        g_wdh[t] = hi; g_wdl[t] = lo;
    }
}

// ================= fused LN1 + gate GEMM =================
// grid 128, 512 thr, 256 tokens/CTA
// smem el: Ah 0 (256x136), Al 34816, Wh 69632 (512x40), Wl 90112; total 110592 el
#define GXS_SMEM (110592*2)
__global__ void __launch_bounds__(512,1) k_gx(int blk, const float* __restrict__ lnw){
    extern __shared__ bf16 smg[];
    bf16 *Ah = smg, *Al = smg + 34816, *Wh = smg + 69632, *Wl = smg + 90112;
    int tid = threadIdx.x, w = tid>>5, lane = tid&31;
    const bf16* wh = g_wgh + blk*16384;
    const bf16* wl = g_wgl + blk*16384;
    for (int i = tid; i < 2048; i += 512){
        int r = i>>2, c8 = (i&3)*8;
        *reinterpret_cast<uint4*>(Wh + r*40 + c8) = *reinterpret_cast<const uint4*>(wh + r*32 + c8);
        *reinterpret_cast<uint4*>(Wl + r*40 + c8) = *reinterpret_cast<const uint4*>(wl + r*32 + c8);
    }
    int t0 = blockIdx.x*256;
    float4 lw = reinterpret_cast<const float4*>(lnw)[lane];
    #pragma unroll 1
    for (int i = 0; i < 16; i++){
        int tok = w*16 + i;
        ln_row(g_h + (size_t)(t0+tok)*128, lw, lane, Ah, Al, tok);
    }
    __syncthreads();

    int gr = lane>>2, gc = (lane&3)*2;
    int r7 = lane&7, g2 = (lane>>3)&1, g4 = lane>>4;
    uint32_t aoff = (uint32_t)(((g2*8 + r7)*136 + g4*8)*2);
    uint32_t boff = (uint32_t)((r7*40 + g2*8)*2);
    uint32_t sAh = s2u(Ah), sAl = s2u(Al), sWh = s2u(Wh), sWl = s2u(Wl);
    int m0 = (w&7)*32;
    int nhalf = w>>3;
    #pragma unroll 1
    for (int it = 0; it < 4; it++){
        int ng = nhalf*4 + it;
        int head = ng>>1;
        int nb = ng*64;
        float acc[2][8][4];
        #pragma unroll
        for (int ms=0;ms<2;ms++)
            #pragma unroll
            for (int nt=0;nt<8;nt++)
                #pragma unroll
                for (int i=0;i<4;i++) acc[ms][nt][i]=0.f;
        #pragma unroll
        for (int kc = 0; kc < 2; kc++){
            int k0 = head*32 + kc*16;
            uint32_t ab = (uint32_t)((m0*136 + k0)*2);
            uint32_t ah0[4], ah1[4], al0[4], al1[4];
            ldsm4(ah0, sAh + ab + aoff);
            ldsm4(ah1, sAh + ab + 16u*136u*2u + aoff);
            ldsm4(al0, sAl + ab + aoff);
            ldsm4(al1, sAl + ab + 16u*136u*2u + aoff);
            uint32_t wb0 = (uint32_t)(kc*16*2);
            #pragma unroll
            for (int nt = 0; nt < 8; nt++){
                int nr = nb + nt*8;
                uint32_t bb = (uint32_t)(nr*40*2) + wb0 + boff;
                uint32_t bh[2], bl[2];
                ldsm2(bh, sWh + bb);
                ldsm2(bl, sWl + bb);
                mma3(acc[0][nt], ah0, al0, bh, bl);
                mma3(acc[1][nt], ah1, al1, bh, bl);
            }
        }
        #pragma unroll
        for (int ms=0;ms<2;ms++){
            int tA = t0 + m0 + ms*16 + gr;
            int tB = tA + 8;
            int bA = tA>>6, sA = tA&63;
            int bB = tB>>6, sB = tB&63;
            float* dA = &g_gx[((size_t)(sA*Bm + bA))*512];
            float* dB = &g_gx[((size_t)(sB*Bm + bB))*512];
            #pragma unroll
            for (int nt=0;nt<8;nt++){
                int col = nb + nt*8 + gc;
                *reinterpret_cast<float2*>(dA + col) = make_float2(acc[ms][nt][0], acc[ms][nt][1]);
                *reinterpret_cast<float2*>(dB + col) = make_float2(acc[ms][nt][2], acc[ms][nt][3]);
            }
        }
    }
}

// ================= fused LN2 + FF up + GeGLU -> split v =================
// grid 128, 512 thr, 2 m-tiles of 128 tokens
// smem el: Ah 0 (128x136), Al 17408, Wh 34816 (256x136), Wl 69632; total 104448 el
#define UPS_SMEM (104448*2)
__global__ void __launch_bounds__(512,1) k_up(int blk, const float* __restrict__ lnw){
    extern __shared__ bf16 smu[];
    bf16 *Ah = smu, *Al = smu + 17408, *Wh = smu + 34816, *Wl = smu + 69632;
    int tid = threadIdx.x, w = tid>>5, lane = tid&31;
    const bf16* wh = g_wuh + blk*32768;
    const bf16* wl = g_wul + blk*32768;
    for (int i = tid; i < 4096; i += 512){
        int r = i>>4, c8 = (i&15)*8;
        *reinterpret_cast<uint4*>(Wh + r*136 + c8) = *reinterpret_cast<const uint4*>(wh + r*128 + c8);
        *reinterpret_cast<uint4*>(Wl + r*136 + c8) = *reinterpret_cast<const uint4*>(wl + r*128 + c8);
    }
    float4 lw = reinterpret_cast<const float4*>(lnw)[lane];
    int gr = lane>>2, gc = (lane&3)*2;
    int r7 = lane&7, g2 = (lane>>3)&1, g4 = lane>>4;
    uint32_t aoff = (uint32_t)(((g2*8 + r7)*136 + g4*8)*2);
    uint32_t boff = (uint32_t)((r7*136 + g2*8)*2);
    uint32_t sAh = s2u(Ah), sAl = s2u(Al), sWh = s2u(Wh), sWl = s2u(Wl);
    int m0 = (w&3)*32;
    int j0 = (w>>2)*32;
    #pragma unroll 1
    for (int mt = 0; mt < 2; mt++){
        int t0 = (blockIdx.x*2 + mt)*128;
        __syncthreads();
        #pragma unroll 1
        for (int i = 0; i < 8; i++){
            int tok = w*8 + i;
            ln_row(g_h + (size_t)(t0+tok)*128, lw, lane, Ah, Al, tok);
        }
        __syncthreads();
        float ga[2][4][4], ua[2][4][4];
        #pragma unroll
        for (int ms=0;ms<2;ms++)
            #pragma unroll
            for (int nt=0;nt<4;nt++)
                #pragma unroll
                for (int i=0;i<4;i++){ ga[ms][nt][i]=0.f; ua[ms][nt][i]=0.f; }
        #pragma unroll
        for (int kc = 0; kc < 8; kc++){
            int k0 = kc*16;
            uint32_t ab = (uint32_t)((m0*136 + k0)*2);
            uint32_t ah0[4], ah1[4], al0[4], al1[4];
            ldsm4(ah0, sAh + ab + aoff);
            ldsm4(ah1, sAh + ab + 16u*136u*2u + aoff);
            ldsm4(al0, sAl + ab + aoff);
            ldsm4(al1, sAl + ab + 16u*136u*2u + aoff);
            #pragma unroll
            for (int nt = 0; nt < 4; nt++){
                int jr = j0 + nt*8;
                uint32_t bbg = (uint32_t)((jr*136 + k0)*2) + boff;
                uint32_t bbu = (uint32_t)(((128+jr)*136 + k0)*2) + boff;
                uint32_t bgh[2], bgl[2], buh[2], bul[2];
                ldsm2(bgh, sWh + bbg);
                ldsm2(bgl, sWl + bbg);
                ldsm2(buh, sWh + bbu);
                ldsm2(bul, sWl + bbu);
                mma3(ga[0][nt], ah0, al0, bgh, bgl);
                mma3(ga[1][nt], ah1, al1, bgh, bgl);
                mma3(ua[0][nt], ah0, al0, buh, bul);
                mma3(ua[1][nt], ah1, al1, buh, bul);
            }
        }
        #pragma unroll
        for (int ms=0;ms<2;ms++){
            size_t rA = (size_t)(t0 + m0 + ms*16 + gr)*128;
            size_t rB = rA + 8*128;
            #pragma unroll
            for (int nt=0;nt<4;nt++){
                int col = j0 + nt*8 + gc;
                float v0 = gelu_(ga[ms][nt][0])*ua[ms][nt][0];
                float v1 = gelu_(ga[ms][nt][1])*ua[ms][nt][1];
                float v2 = gelu_(ga[ms][nt][2])*ua[ms][nt][2];
                float v3 = gelu_(ga[ms][nt][3])*ua[ms][nt][3];
                bf16 h0,l0,h1,l1,h2,l2,h3,l3;
                bsplit(v0,h0,l0); bsplit(v1,h1,l1); bsplit(v2,h2,l2); bsplit(v3,h3,l3);
                __nv_bfloat162 p0; p0.x=h0; p0.y=h1;
                __nv_bfloat162 p1; p1.x=h2; p1.y=h3;
                __nv_bfloat162 q0; q0.x=l0; q0.y=l1;
                __nv_bfloat162 q1; q1.x=l2; q1.y=l3;
                *reinterpret_cast<__nv_bfloat162*>(&g_vh[rA + col]) = p0;
                *reinterpret_cast<__nv_bfloat162*>(&g_vh[rB + col]) = p1;
                *reinterpret_cast<__nv_bfloat162*>(&g_vl[rA + col]) = q0;
                *reinterpret_cast<__nv_bfloat162*>(&g_vl[rB + col]) = q1;
            }
        }
    }
}

// ================= FF down + residual =================
// grid 128, 512 thr, 2 m-tiles of 128 tokens
// smem el: Ah 0, Al 17408, Wh 34816 (128x136), Wl 52224; total 69632 el
#define DNS_SMEM (69632*2)
__global__ void __launch_bounds__(512,1) k_down(int blk){
    extern __shared__ bf16 smd[];
    bf16 *Ah = smd, *Al = smd + 17408, *Wh = smd + 34816, *Wl = smd + 52224;
    int tid = threadIdx.x, w = tid>>5, lane = tid&31;
    const bf16* wh = g_wdh + blk*16384;
    const bf16* wl = g_wdl + blk*16384;
    for (int i = tid; i < 2048; i += 512){
        int r = i>>4, c8 = (i&15)*8;
        *reinterpret_cast<uint4*>(Wh + r*136 + c8) = *reinterpret_cast<const uint4*>(wh + r*128 + c8);
        *reinterpret_cast<uint4*>(Wl + r*136 + c8) = *reinterpret_cast<const uint4*>(wl + r*128 + c8);
    }
    int gr = lane>>2, gc = (lane&3)*2;
    int r7 = lane&7, g2 = (lane>>3)&1, g4 = lane>>4;
    uint32_t aoff = (uint32_t)(((g2*8 + r7)*136 + g4*8)*2);
    uint32_t boff = (uint32_t)((r7*136 + g2*8)*2);
    uint32_t sAh = s2u(Ah), sAl = s2u(Al), sWh = s2u(Wh), sWl = s2u(Wl);
    int m0 = (w&3)*32;
    int nb = (w>>2)*32;
    #pragma unroll 1
    for (int mt = 0; mt < 2; mt++){
        int t0 = (blockIdx.x*2 + mt)*128;
        __syncthreads();
        for (int i = tid; i < 2048; i += 512){
            int r = i>>4, c8 = (i&15)*8;
            *reinterpret_cast<uint4*>(Ah + r*136 + c8) = *reinterpret_cast<const uint4*>(g_vh + (size_t)(t0+r)*128 + c8);
            *reinterpret_cast<uint4*>(Al + r*136 + c8) = *reinterpret_cast<const uint4*>(g_vl + (size_t)(t0+r)*128 + c8);
        }
        __syncthreads();
        float acc[2][4][4];
        #pragma unroll
        for (int ms=0;ms<2;ms++)
            #pragma unroll
            for (int nt=0;nt<4;nt++)
                #pragma unroll
                for (int i=0;i<4;i++) acc[ms][nt][i]=0.f;
        #pragma unroll
        for (int kc = 0; kc < 8; kc++){
            int k0 = kc*16;
            uint32_t ab = (uint32_t)((m0*136 + k0)*2);
            uint32_t ah0[4], ah1[4], al0[4], al1[4];
            ldsm4(ah0, sAh + ab + aoff);
            ldsm4(ah1, sAh + ab + 16u*136u*2u + aoff);
            ldsm4(al0, sAl + ab + aoff);
            ldsm4(al1, sAl + ab + 16u*136u*2u + aoff);
            #pragma unroll
            for (int nt = 0; nt < 4; nt++){
                int nr = nb + nt*8;
                uint32_t bb = (uint32_t)((nr*136 + k0)*2) + boff;
                uint32_t bh[2], bl[2];
                ldsm2(bh, sWh + bb);
                ldsm2(bl, sWl + bb);
                mma3(acc[0][nt], ah0, al0, bh, bl);
                mma3(acc[1][nt], ah1, al1, bh, bl);
            }
        }
        #pragma unroll
        for (int ms=0;ms<2;ms++){
            size_t rA = (size_t)(t0 + m0 + ms*16 + gr)*128;
            size_t rB = rA + 8*128;
            #pragma unroll
            for (int nt=0;nt<4;nt++){
                int col = nb + nt*8 + gc;
                float2* pA = reinterpret_cast<float2*>(&g_h[rA + col]);
                float2* pB = reinterpret_cast<float2*>(&g_h[rB + col]);
                float2 hA = *pA, hB = *pB;
                hA.x += acc[ms][nt][0]; hA.y += acc[ms][nt][1];
                hB.x += acc[ms][nt][2]; hB.y += acc[ms][nt][3];
                *pA = hA; *pB = hB;
            }
        }
    }
}

// ---------------- sLSTM gate math ----------------
__device__ __forceinline__ float slstm_step(float i_r, float f_r, float z_r, float o_r,
                                            float& c, float& nn, float& m){
    float lsf = (f_r >= 0.f) ? (-__logf(1.f + __expf(-f_r)))
                             : (f_r - __logf(1.f + __expf(f_r)));
    float lfm = m + lsf;
    float mnew = fmaxf(i_r, lfm);
    float ig = __expf(i_r - mnew);
    float fg = __expf(lfm - mnew);
    float e2z = __expf(2.f*z_r);
    float tz = 1.f - 2.f/(e2z + 1.f);
    c  = fg*c  + ig*tz;
    nn = fg*nn + ig;
    m  = mnew;
    float so = 1.f/(1.f + __expf(-o_r));
    return so * c / nn;
}

// ================= sequential scan =================
__global__ void __launch_bounds__(128,2) k_scan(const float* __restrict__ Rw,
                                                const float* __restrict__ bw,
                                                const float* __restrict__ gnw){
    __shared__ __align__(16) float hs[1024];
    int tid = threadIdx.x;
    int n = tid >> 5, k = tid & 31;
    int b0 = blockIdx.x*2, b1 = b0 + 1;

    ull r01[32], r23[32];
    const float* rp = Rw + n*4096 + k;
    #pragma unroll
    for (int h = 0; h < 32; h++){
        r01[h] = pk2(rp[h*128],      rp[h*128 + 32]);
        r23[h] = pk2(rp[h*128 + 64], rp[h*128 + 96]);
    }
    float bias0 = bw[(n*4+0)*32+k], bias1 = bw[(n*4+1)*32+k];
    float bias2 = bw[(n*4+2)*32+k], bias3 = bw[(n*4+3)*32+k];
    float gw = gnw[n*32+k];

    int o = n*32 + k;
    *reinterpret_cast<ull*>(&hs[o*2])       = 0ull;
    *reinterpret_cast<ull*>(&hs[256 + o*2]) = 0ull;
    float ca=0.f, na=0.f, ma=0.f, cb=0.f, nb=0.f, mb=0.f;
    __syncwarp();

    const float4* pga = reinterpret_cast<const float4*>(&g_gx[(size_t)b0*512 + o*4]);
    const float4* pgb = reinterpret_cast<const float4*>(&g_gx[(size_t)b1*512 + o*4]);
    float4 ga = pga[0], gb = pgb[0];
    int cur = 0;

    for (int s = 0; s < Sm; s++){
        float4 gan = ga, gbn = gb;
        if (s < Sm-1){ gan = pga[(s+1)*65536]; gbn = pgb[(s+1)*65536]; }
        ull aa01=0, aa23=0, ab01=0, ab23=0;
        const ulonglong2* hpa = reinterpret_cast<const ulonglong2*>(&hs[cur*512 + n*64]);
        const ulonglong2* hpb = reinterpret_cast<const ulonglong2*>(&hs[cur*512 + 256 + n*64]);
        #pragma unroll
        for (int hh = 0; hh < 16; hh++){
            ulonglong2 ha = hpa[hh];
            ulonglong2 hb = hpb[hh];
            aa01 = fma2_(ha.x, r01[2*hh],   aa01);
            aa23 = fma2_(ha.x, r23[2*hh],   aa23);
            ab01 = fma2_(hb.x, r01[2*hh],   ab01);
            ab23 = fma2_(hb.x, r23[2*hh],   ab23);
            aa01 = fma2_(ha.y, r01[2*hh+1], aa01);
            aa23 = fma2_(ha.y, r23[2*hh+1], aa23);
            ab01 = fma2_(hb.y, r01[2*hh+1], ab01);
            ab23 = fma2_(hb.y, r23[2*hh+1], ab23);
        }
        float ria,rfa,rza,roa, rib,rfb,rzb,rob;
        upk2(aa01,ria,rfa); upk2(aa23,rza,roa);
        upk2(ab01,rib,rfb); upk2(ab23,rzb,rob);
        float hn_a = slstm_step(ria+ga.x+bias0, rfa+ga.y+bias1, rza+ga.z+bias2, roa+ga.w+bias3, ca,na,ma);
        float hn_b = slstm_step(rib+gb.x+bias0, rfb+gb.y+bias1, rzb+gb.z+bias2, rob+gb.w+bias3, cb,nb,mb);
        int nxt = cur ^ 1;
        *reinterpret_cast<ull*>(&hs[nxt*512 + o*2])       = pk2(hn_a, hn_a);
        *reinterpret_cast<ull*>(&hs[nxt*512 + 256 + o*2]) = pk2(hn_b, hn_b);
        __syncwarp();
        float sa = hn_a, qa = hn_a*hn_a, sb2 = hn_b, qb = hn_b*hn_b;
        #pragma unroll
        for (int off=16; off>0; off>>=1){
            sa  += __shfl_xor_sync(0xffffffffu,sa,off);
            qa  += __shfl_xor_sync(0xffffffffu,qa,off);
            sb2 += __shfl_xor_sync(0xffffffffu,sb2,off);
            qb  += __shfl_xor_sync(0xffffffffu,qb,off);
        }
        float mua = sa*(1.f/32.f);
        float inva = rsqrtf(qa*(1.f/32.f) - mua*mua + EPSm);
        float mub = sb2*(1.f/32.f);
        float invb = rsqrtf(qb*(1.f/32.f) - mub*mub + EPSm);
        g_h[(size_t)(b0*64+s)*Dm + o] += (hn_a - mua)*inva*gw;
        g_h[(size_t)(b1*64+s)*Dm + o] += (hn_b - mub)*invb*gw;
        ga = gan; gb = gbn;
        cur = nxt;
    }
}

// ---------------- final LN + vocab projection ----------------
__global__ void k_proj(const float* __restrict__ pw_ln, const float* __restrict__ pjw,
                       const float* __restrict__ pjb, float* __restrict__ out){
    int gt = blockIdx.x*8 + (threadIdx.x>>5);
    int lane = threadIdx.x & 31;
    float4 v = reinterpret_cast<const float4*>(g_h + (size_t)gt*Dm)[lane];
    float s = v.x+v.y+v.z+v.w;
    float q = v.x*v.x+v.y*v.y+v.z*v.z+v.w*v.w;
    #pragma unroll
    for (int o=16;o>0;o>>=1){ s += __shfl_xor_sync(0xffffffffu,s,o); q += __shfl_xor_sync(0xffffffffu,q,o); }
    float mu = s*(1.f/128.f);
    float inv = rsqrtf(q*(1.f/128.f) - mu*mu + EPSm);
    float4 wv = reinterpret_cast<const float4*>(pw_ln)[lane];
    float4 xv;
    xv.x=(v.x-mu)*inv*wv.x; xv.y=(v.y-mu)*inv*wv.y;
    xv.z=(v.z-mu)*inv*wv.z; xv.w=(v.w-mu)*inv*wv.w;
    float res = 0.f;
    #pragma unroll
    for (int vc = 0; vc < 9; vc++){
        float4 p = reinterpret_cast<const float4*>(pjw + vc*Dm)[lane];
        float sv = xv.x*p.x + xv.y*p.y + xv.z*p.z + xv.w*p.w;
        #pragma unroll
        for (int o=16;o>0;o>>=1) sv += __shfl_xor_sync(0xffffffffu,sv,o);
        if (lane == vc) res = sv;
    }
    if (lane < 9) out[gt*9 + lane] = res + pjb[lane];
}

// ---------------- launch ----------------
extern "C" void kernel_launch(void* const* d_in, const int* in_sizes, int n_in,
                              void* d_out, int out_size){
    const int*   x      = (const int*)  d_in[0];
    const float* emb    = (const float*)d_in[1];
    const float* ln1_w  = (const float*)d_in[2];
    const float* Wg     = (const float*)d_in[3];
    const float* R      = (const float*)d_in[4];
    const float* bias   = (const float*)d_in[5];
    const float* gn_w   = (const float*)d_in[6];
    const float* ln2_w  = (const float*)d_in[7];
    const float* ffu    = (const float*)d_in[8];
    const float* ffd    = (const float*)d_in[9];
    const float* post_w = (const float*)d_in[10];
    const float* pjw    = (const float*)d_in[11];
    const float* pjb    = (const float*)d_in[12];
    float* out = (float*)d_out;

    cudaFuncSetAttribute(k_gx,   cudaFuncAttributeMaxDynamicSharedMemorySize, GXS_SMEM);
    cudaFuncSetAttribute(k_up,   cudaFuncAttributeMaxDynamicSharedMemorySize, UPS_SMEM);
    cudaFuncSetAttribute(k_down, cudaFuncAttributeMaxDynamicSharedMemorySize, DNS_SMEM);

    k_embed<<<4096,256>>>(x, emb);
    k_prep <<<512,256>>>(Wg, ffu, ffd);
    for (int bi = 0; bi < 2; bi++){
        k_gx  <<<128,512,GXS_SMEM>>>(bi, ln1_w + bi*Dm);
        k_scan<<<256,128>>>(R + bi*16384, bias + bi*512, gn_w + bi*Dm);
        k_up  <<<128,512,UPS_SMEM>>>(bi, ln2_w + bi*Dm);
        k_down<<<128,512,DNS_SMEM>>>(bi);
    }
    k_proj<<<4096,256>>>(post_w, pjw, pjb, out);
}

// round 11
// speedup vs baseline: 3.3235x; 1.2868x over previous
#include <cuda_runtime.h>
#include <cuda_bf16.h>
#include <math.h>
#include <stdint.h>
#include <cstdint>

#define Bm 512
#define Sm 64
#define Dm 128
#define EPSm 1e-5f
typedef unsigned long long ull;
typedef __nv_bfloat16 bf16;

// ---------------- scratch ----------------
__device__ float g_h[Bm*Sm*Dm];
__device__ float g_gx[(size_t)Sm*Bm*512];
__device__ __align__(16) bf16 g_vh[Bm*Sm*Dm], g_vl[Bm*Sm*Dm];
__device__ __align__(16) bf16 g_wgh[2*512*32],  g_wgl[2*512*32];   // [blk][o=n*128+k*4+g][h]
__device__ __align__(16) bf16 g_wuh[2*256*128], g_wul[2*256*128];  // [blk][out][in]
__device__ __align__(16) bf16 g_wdh[2*128*128], g_wdl[2*128*128];  // [blk][out][in]

// ---------------- f32x2 helpers (scan) ----------------
__device__ __forceinline__ ull pk2(float a, float b){ ull r; asm("mov.b64 %0, {%1,%2};" : "=l"(r) : "f"(a), "f"(b)); return r; }
__device__ __forceinline__ void upk2(ull v, float &a, float &b){ asm("mov.b64 {%0,%1}, %2;" : "=f"(a), "=f"(b) : "l"(v)); }
__device__ __forceinline__ ull fma2_(ull a, ull b, ull c){ ull d; asm("fma.rn.f32x2 %0, %1, %2, %3;" : "=l"(d) : "l"(a), "l"(b), "l"(c)); return d; }
__device__ __forceinline__ ull add2_(ull a, ull b){ ull d; asm("add.rn.f32x2 %0, %1, %2;" : "=l"(d) : "l"(a), "l"(b)); return d; }

// ---------------- mma helpers ----------------
__device__ __forceinline__ uint32_t s2u(const void* p){ return (uint32_t)__cvta_generic_to_shared(p); }
__device__ __forceinline__ void mma_bf16(float* c, const uint32_t* a, const uint32_t* b){
    asm("mma.sync.aligned.m16n8k16.row.col.f32.bf16.bf16.f32 "
        "{%0,%1,%2,%3}, {%4,%5,%6,%7}, {%8,%9}, {%0,%1,%2,%3};"
        : "+f"(c[0]), "+f"(c[1]), "+f"(c[2]), "+f"(c[3])
        : "r"(a[0]), "r"(a[1]), "r"(a[2]), "r"(a[3]), "r"(b[0]), "r"(b[1]));
}
__device__ __forceinline__ void ldsm4(uint32_t* r, uint32_t addr){
    asm volatile("ldmatrix.sync.aligned.m8n8.x4.shared.b16 {%0,%1,%2,%3}, [%4];"
        : "=r"(r[0]),"=r"(r[1]),"=r"(r[2]),"=r"(r[3]) : "r"(addr));
}
__device__ __forceinline__ void ldsm2(uint32_t* r, uint32_t addr){
    asm volatile("ldmatrix.sync.aligned.m8n8.x2.shared.b16 {%0,%1}, [%2];"
        : "=r"(r[0]),"=r"(r[1]) : "r"(addr));
}
__device__ __forceinline__ void mma3(float* c, const uint32_t* ah, const uint32_t* al,
                                     const uint32_t* bh, const uint32_t* bl){
    mma_bf16(c, ah, bh);
    mma_bf16(c, ah, bl);
    mma_bf16(c, al, bh);
}
__device__ __forceinline__ void bsplit(float x, bf16& h, bf16& l){
    h = __float2bfloat16(x);
    l = __float2bfloat16(x - __bfloat162float(h));
}
__device__ __forceinline__ float gelu_(float g){
    return 0.5f*g*(1.f + erff(g*0.70710678118f));
}

// LN one token (warp-collective) -> split bf16 into padded smem row (stride 136)
__device__ __forceinline__ void ln_row(const float* __restrict__ hrow, float4 lw, int lane,
                                       bf16* Ah, bf16* Al, int tok){
    float4 v = reinterpret_cast<const float4*>(hrow)[lane];
    float s = v.x+v.y+v.z+v.w;
    float q = v.x*v.x+v.y*v.y+v.z*v.z+v.w*v.w;
    #pragma unroll
    for (int o=16;o>0;o>>=1){ s += __shfl_xor_sync(0xffffffffu,s,o); q += __shfl_xor_sync(0xffffffffu,q,o); }
    float mu = s*(1.f/128.f);
    float inv = rsqrtf(q*(1.f/128.f) - mu*mu + EPSm);
    float x0=(v.x-mu)*inv*lw.x, x1=(v.y-mu)*inv*lw.y;
    float x2=(v.z-mu)*inv*lw.z, x3=(v.w-mu)*inv*lw.w;
    bf16 h0,l0,h1,l1,h2,l2,h3,l3;
    bsplit(x0,h0,l0); bsplit(x1,h1,l1); bsplit(x2,h2,l2); bsplit(x3,h3,l3);
    int base = tok*136 + lane*4;
    __nv_bfloat162 p0; p0.x=h0; p0.y=h1;
    __nv_bfloat162 p1; p1.x=h2; p1.y=h3;
    __nv_bfloat162 q0; q0.x=l0; q0.y=l1;
    __nv_bfloat162 q1; q1.x=l2; q1.y=l3;
    *reinterpret_cast<__nv_bfloat162*>(Ah+base)   = p0;
    *reinterpret_cast<__nv_bfloat162*>(Ah+base+2) = p1;
    *reinterpret_cast<__nv_bfloat162*>(Al+base)   = q0;
    *reinterpret_cast<__nv_bfloat162*>(Al+base+2) = q1;
}

// ---------------- fused embedding + weight prep ----------------
__global__ void k_pre(const int* __restrict__ x, const float* __restrict__ emb,
                      const float* __restrict__ wg, const float* __restrict__ wu,
                      const float* __restrict__ wd){
    if (blockIdx.x < 4096){
        int i = blockIdx.x*256 + threadIdx.x;
        int t = i >> 5, d4 = i & 31;
        int v = x[t];
        reinterpret_cast<float4*>(g_h)[t*32 + d4] =
            reinterpret_cast<const float4*>(emb)[v*32 + d4];
        return;
    }
    int id = (blockIdx.x - 4096)*256 + threadIdx.x;   // 131072 total
    if (id < 32768){
        int blk = id >> 14, rem = id & 16383;
        int o = rem >> 5, h = rem & 31;
        int n = o >> 7, r = o & 127, kk = r >> 2, g = r & 3;
        float val = wg[(((blk*4 + g)*4 + n)*32 + kk)*32 + h];
        bf16 hi, lo; bsplit(val, hi, lo);
        g_wgh[id] = hi; g_wgl[id] = lo;
    } else if (id < 98304){
        int t = id - 32768;
        bf16 hi, lo; bsplit(wu[t], hi, lo);
        g_wuh[t] = hi; g_wul[t] = lo;
    } else {
        int t = id - 98304;
        bf16 hi, lo; bsplit(wd[t], hi, lo);
        g_wdh[t] = hi; g_wdl[t] = lo;
    }
}

// ================= fused LN1 + gate GEMM =================
// grid 128, 512 thr, 256 tokens/CTA
// smem el: Ah 0 (256x136), Al 34816, Wh 69632 (512x40), Wl 90112; total 110592 el
#define GXS_SMEM (110592*2)
__global__ void __launch_bounds__(512,1) k_gx(int blk, const float* __restrict__ lnw){
    extern __shared__ bf16 smg[];
    bf16 *Ah = smg, *Al = smg + 34816, *Wh = smg + 69632, *Wl = smg + 90112;
    int tid = threadIdx.x, w = tid>>5, lane = tid&31;
    const bf16* wh = g_wgh + blk*16384;
    const bf16* wl = g_wgl + blk*16384;
    for (int i = tid; i < 2048; i += 512){
        int r = i>>2, c8 = (i&3)*8;
        *reinterpret_cast<uint4*>(Wh + r*40 + c8) = *reinterpret_cast<const uint4*>(wh + r*32 + c8);
        *reinterpret_cast<uint4*>(Wl + r*40 + c8) = *reinterpret_cast<const uint4*>(wl + r*32 + c8);
    }
    int t0 = blockIdx.x*256;
    float4 lw = reinterpret_cast<const float4*>(lnw)[lane];
    #pragma unroll 1
    for (int i = 0; i < 16; i++){
        int tok = w*16 + i;
        ln_row(g_h + (size_t)(t0+tok)*128, lw, lane, Ah, Al, tok);
    }
    __syncthreads();

    int gr = lane>>2, gc = (lane&3)*2;
    int r7 = lane&7, g2 = (lane>>3)&1, g4 = lane>>4;
    uint32_t aoff = (uint32_t)(((g2*8 + r7)*136 + g4*8)*2);
    uint32_t boff = (uint32_t)((r7*40 + g2*8)*2);
    uint32_t sAh = s2u(Ah), sAl = s2u(Al), sWh = s2u(Wh), sWl = s2u(Wl);
    int m0 = (w&7)*32;
    int nhalf = w>>3;
    #pragma unroll 1
    for (int it = 0; it < 4; it++){
        int ng = nhalf*4 + it;
        int head = ng>>1;
        int nb = ng*64;
        float acc[2][8][4];
        #pragma unroll
        for (int ms=0;ms<2;ms++)
            #pragma unroll
            for (int nt=0;nt<8;nt++)
                #pragma unroll
                for (int i=0;i<4;i++) acc[ms][nt][i]=0.f;
        #pragma unroll
        for (int kc = 0; kc < 2; kc++){
            int k0 = head*32 + kc*16;
            uint32_t ab = (uint32_t)((m0*136 + k0)*2);
            uint32_t ah0[4], ah1[4], al0[4], al1[4];
            ldsm4(ah0, sAh + ab + aoff);
            ldsm4(ah1, sAh + ab + 16u*136u*2u + aoff);
            ldsm4(al0, sAl + ab + aoff);
            ldsm4(al1, sAl + ab + 16u*136u*2u + aoff);
            uint32_t wb0 = (uint32_t)(kc*16*2);
            #pragma unroll
            for (int nt = 0; nt < 8; nt++){
                int nr = nb + nt*8;
                uint32_t bb = (uint32_t)(nr*40*2) + wb0 + boff;
                uint32_t bh[2], bl[2];
                ldsm2(bh, sWh + bb);
                ldsm2(bl, sWl + bb);
                mma3(acc[0][nt], ah0, al0, bh, bl);
                mma3(acc[1][nt], ah1, al1, bh, bl);
            }
        }
        #pragma unroll
        for (int ms=0;ms<2;ms++){
            int tA = t0 + m0 + ms*16 + gr;
            int tB = tA + 8;
            int bA = tA>>6, sA = tA&63;
            int bB = tB>>6, sB = tB&63;
            float* dA = &g_gx[((size_t)(sA*Bm + bA))*512];
            float* dB = &g_gx[((size_t)(sB*Bm + bB))*512];
            #pragma unroll
            for (int nt=0;nt<8;nt++){
                int col = nb + nt*8 + gc;
                *reinterpret_cast<float2*>(dA + col) = make_float2(acc[ms][nt][0], acc[ms][nt][1]);
                *reinterpret_cast<float2*>(dB + col) = make_float2(acc[ms][nt][2], acc[ms][nt][3]);
            }
        }
    }
}

// ================= fused LN2 + FF up + GeGLU -> split v =================
// grid 128, 512 thr, 2 m-tiles of 128 tokens
// smem el: Ah 0 (128x136), Al 17408, Wh 34816 (256x136), Wl 69632; total 104448 el
#define UPS_SMEM (104448*2)
__global__ void __launch_bounds__(512,1) k_up(int blk, const float* __restrict__ lnw){
    extern __shared__ bf16 smu[];
    bf16 *Ah = smu, *Al = smu + 17408, *Wh = smu + 34816, *Wl = smu + 69632;
    int tid = threadIdx.x, w = tid>>5, lane = tid&31;
    const bf16* wh = g_wuh + blk*32768;
    const bf16* wl = g_wul + blk*32768;
    for (int i = tid; i < 4096; i += 512){
        int r = i>>4, c8 = (i&15)*8;
        *reinterpret_cast<uint4*>(Wh + r*136 + c8) = *reinterpret_cast<const uint4*>(wh + r*128 + c8);
        *reinterpret_cast<uint4*>(Wl + r*136 + c8) = *reinterpret_cast<const uint4*>(wl + r*128 + c8);
    }
    float4 lw = reinterpret_cast<const float4*>(lnw)[lane];
    int gr = lane>>2, gc = (lane&3)*2;
    int r7 = lane&7, g2 = (lane>>3)&1, g4 = lane>>4;
    uint32_t aoff = (uint32_t)(((g2*8 + r7)*136 + g4*8)*2);
    uint32_t boff = (uint32_t)((r7*136 + g2*8)*2);
    uint32_t sAh = s2u(Ah), sAl = s2u(Al), sWh = s2u(Wh), sWl = s2u(Wl);
    int m0 = (w&3)*32;
    int j0 = (w>>2)*32;
    #pragma unroll 1
    for (int mt = 0; mt < 2; mt++){
        int t0 = (blockIdx.x*2 + mt)*128;
        __syncthreads();
        #pragma unroll 1
        for (int i = 0; i < 8; i++){
            int tok = w*8 + i;
            ln_row(g_h + (size_t)(t0+tok)*128, lw, lane, Ah, Al, tok);
        }
        __syncthreads();
        float ga[2][4][4], ua[2][4][4];
        #pragma unroll
        for (int ms=0;ms<2;ms++)
            #pragma unroll
            for (int nt=0;nt<4;nt++)
                #pragma unroll
                for (int i=0;i<4;i++){ ga[ms][nt][i]=0.f; ua[ms][nt][i]=0.f; }
        #pragma unroll
        for (int kc = 0; kc < 8; kc++){
            int k0 = kc*16;
            uint32_t ab = (uint32_t)((m0*136 + k0)*2);
            uint32_t ah0[4], ah1[4], al0[4], al1[4];
            ldsm4(ah0, sAh + ab + aoff);
            ldsm4(ah1, sAh + ab + 16u*136u*2u + aoff);
            ldsm4(al0, sAl + ab + aoff);
            ldsm4(al1, sAl + ab + 16u*136u*2u + aoff);
            #pragma unroll
            for (int nt = 0; nt < 4; nt++){
                int jr = j0 + nt*8;
                uint32_t bbg = (uint32_t)((jr*136 + k0)*2) + boff;
                uint32_t bbu = (uint32_t)(((128+jr)*136 + k0)*2) + boff;
                uint32_t bgh[2], bgl[2], buh[2], bul[2];
                ldsm2(bgh, sWh + bbg);
                ldsm2(bgl, sWl + bbg);
                ldsm2(buh, sWh + bbu);
                ldsm2(bul, sWl + bbu);
                mma3(ga[0][nt], ah0, al0, bgh, bgl);
                mma3(ga[1][nt], ah1, al1, bgh, bgl);
                mma3(ua[0][nt], ah0, al0, buh, bul);
                mma3(ua[1][nt], ah1, al1, buh, bul);
            }
        }
        #pragma unroll
        for (int ms=0;ms<2;ms++){
            size_t rA = (size_t)(t0 + m0 + ms*16 + gr)*128;
            size_t rB = rA + 8*128;
            #pragma unroll
            for (int nt=0;nt<4;nt++){
                int col = j0 + nt*8 + gc;
                float v0 = gelu_(ga[ms][nt][0])*ua[ms][nt][0];
                float v1 = gelu_(ga[ms][nt][1])*ua[ms][nt][1];
                float v2 = gelu_(ga[ms][nt][2])*ua[ms][nt][2];
                float v3 = gelu_(ga[ms][nt][3])*ua[ms][nt][3];
                bf16 h0,l0,h1,l1,h2,l2,h3,l3;
                bsplit(v0,h0,l0); bsplit(v1,h1,l1); bsplit(v2,h2,l2); bsplit(v3,h3,l3);
                __nv_bfloat162 p0; p0.x=h0; p0.y=h1;
                __nv_bfloat162 p1; p1.x=h2; p1.y=h3;
                __nv_bfloat162 q0; q0.x=l0; q0.y=l1;
                __nv_bfloat162 q1; q1.x=l2; q1.y=l3;
                *reinterpret_cast<__nv_bfloat162*>(&g_vh[rA + col]) = p0;
                *reinterpret_cast<__nv_bfloat162*>(&g_vh[rB + col]) = p1;
                *reinterpret_cast<__nv_bfloat162*>(&g_vl[rA + col]) = q0;
                *reinterpret_cast<__nv_bfloat162*>(&g_vl[rB + col]) = q1;
            }
        }
    }
}

// ================= FF down + residual =================
// grid 128, 512 thr, 2 m-tiles of 128 tokens
// smem el: Ah 0, Al 17408, Wh 34816 (128x136), Wl 52224; total 69632 el
#define DNS_SMEM (69632*2)
__global__ void __launch_bounds__(512,1) k_down(int blk){
    extern __shared__ bf16 smd[];
    bf16 *Ah = smd, *Al = smd + 17408, *Wh = smd + 34816, *Wl = smd + 52224;
    int tid = threadIdx.x, w = tid>>5, lane = tid&31;
    const bf16* wh = g_wdh + blk*16384;
    const bf16* wl = g_wdl + blk*16384;
    for (int i = tid; i < 2048; i += 512){
        int r = i>>4, c8 = (i&15)*8;
        *reinterpret_cast<uint4*>(Wh + r*136 + c8) = *reinterpret_cast<const uint4*>(wh + r*128 + c8);
        *reinterpret_cast<uint4*>(Wl + r*136 + c8) = *reinterpret_cast<const uint4*>(wl + r*128 + c8);
    }
    int gr = lane>>2, gc = (lane&3)*2;
    int r7 = lane&7, g2 = (lane>>3)&1, g4 = lane>>4;
    uint32_t aoff = (uint32_t)(((g2*8 + r7)*136 + g4*8)*2);
    uint32_t boff = (uint32_t)((r7*136 + g2*8)*2);
    uint32_t sAh = s2u(Ah), sAl = s2u(Al), sWh = s2u(Wh), sWl = s2u(Wl);
    int m0 = (w&3)*32;
    int nb = (w>>2)*32;
    #pragma unroll 1
    for (int mt = 0; mt < 2; mt++){
        int t0 = (blockIdx.x*2 + mt)*128;
        __syncthreads();
        for (int i = tid; i < 2048; i += 512){
            int r = i>>4, c8 = (i&15)*8;
            *reinterpret_cast<uint4*>(Ah + r*136 + c8) = *reinterpret_cast<const uint4*>(g_vh + (size_t)(t0+r)*128 + c8);
            *reinterpret_cast<uint4*>(Al + r*136 + c8) = *reinterpret_cast<const uint4*>(g_vl + (size_t)(t0+r)*128 + c8);
        }
        __syncthreads();
        float acc[2][4][4];
        #pragma unroll
        for (int ms=0;ms<2;ms++)
            #pragma unroll
            for (int nt=0;nt<4;nt++)
                #pragma unroll
                for (int i=0;i<4;i++) acc[ms][nt][i]=0.f;
        #pragma unroll
        for (int kc = 0; kc < 8; kc++){
            int k0 = kc*16;
            uint32_t ab = (uint32_t)((m0*136 + k0)*2);
            uint32_t ah0[4], ah1[4], al0[4], al1[4];
            ldsm4(ah0, sAh + ab + aoff);
            ldsm4(ah1, sAh + ab + 16u*136u*2u + aoff);
            ldsm4(al0, sAl + ab + aoff);
            ldsm4(al1, sAl + ab + 16u*136u*2u + aoff);
            #pragma unroll
            for (int nt = 0; nt < 4; nt++){
                int nr = nb + nt*8;
                uint32_t bb = (uint32_t)((nr*136 + k0)*2) + boff;
                uint32_t bh[2], bl[2];
                ldsm2(bh, sWh + bb);
                ldsm2(bl, sWl + bb);
                mma3(acc[0][nt], ah0, al0, bh, bl);
                mma3(acc[1][nt], ah1, al1, bh, bl);
            }
        }
        #pragma unroll
        for (int ms=0;ms<2;ms++){
            size_t rA = (size_t)(t0 + m0 + ms*16 + gr)*128;
            size_t rB = rA + 8*128;
            #pragma unroll
            for (int nt=0;nt<4;nt++){
                int col = nb + nt*8 + gc;
                float2* pA = reinterpret_cast<float2*>(&g_h[rA + col]);
                float2* pB = reinterpret_cast<float2*>(&g_h[rB + col]);
                float2 hA = *pA, hB = *pB;
                hA.x += acc[ms][nt][0]; hA.y += acc[ms][nt][1];
                hB.x += acc[ms][nt][2]; hB.y += acc[ms][nt][3];
                *pA = hA; *pB = hB;
            }
        }
    }
}

// ---------------- sLSTM gate math (branchless) ----------------
__device__ __forceinline__ float slstm_step(float i_r, float f_r, float z_r, float o_r,
                                            float& c, float& nn, float& m){
    float lsf = fminf(f_r, 0.f) - __logf(1.f + __expf(-fabsf(f_r)));
    float lfm = m + lsf;
    float mnew = fmaxf(i_r, lfm);
    float ig = __expf(i_r - mnew);
    float fg = __expf(lfm - mnew);
    float e2z = __expf(2.f*z_r);
    float tz = 1.f - __fdividef(2.f, e2z + 1.f);
    c  = fg*c  + ig*tz;
    nn = fg*nn + ig;
    m  = mnew;
    float so = __fdividef(1.f, 1.f + __expf(-o_r));
    return so * __fdividef(c, nn);
}

// ================= sequential scan v3 =================
// 8-way accumulator split + early residual loads
__global__ void __launch_bounds__(128,2) k_scan(const float* __restrict__ Rw,
                                                const float* __restrict__ bw,
                                                const float* __restrict__ gnw){
    __shared__ __align__(16) float hs[1024];
    int tid = threadIdx.x;
    int n = tid >> 5, k = tid & 31;
    int b0 = blockIdx.x*2, b1 = b0 + 1;

    ull r01[32], r23[32];
    const float* rp = Rw + n*4096 + k;
    #pragma unroll
    for (int h = 0; h < 32; h++){
        r01[h] = pk2(rp[h*128],      rp[h*128 + 32]);
        r23[h] = pk2(rp[h*128 + 64], rp[h*128 + 96]);
    }
    float bias0 = bw[(n*4+0)*32+k], bias1 = bw[(n*4+1)*32+k];
    float bias2 = bw[(n*4+2)*32+k], bias3 = bw[(n*4+3)*32+k];
    float gw = gnw[n*32+k];

    int o = n*32 + k;
    *reinterpret_cast<ull*>(&hs[o*2])       = 0ull;
    *reinterpret_cast<ull*>(&hs[256 + o*2]) = 0ull;
    float ca=0.f, na=0.f, ma=0.f, cb=0.f, nb=0.f, mb=0.f;
    __syncwarp();

    const float4* pga = reinterpret_cast<const float4*>(&g_gx[(size_t)b0*512 + o*4]);
    const float4* pgb = reinterpret_cast<const float4*>(&g_gx[(size_t)b1*512 + o*4]);
    float* hpA = &g_h[(size_t)(b0*64)*Dm + o];
    float* hpB = &g_h[(size_t)(b1*64)*Dm + o];
    float4 ga = pga[0], gb = pgb[0];
    int cur = 0;

    for (int s = 0; s < Sm; s++){
        // early loads: residual for THIS step (used at tail), gx for NEXT step
        float hresA = hpA[s*Dm];
        float hresB = hpB[s*Dm];
        float4 gan = ga, gbn = gb;
        if (s < Sm-1){ gan = pga[(s+1)*65536]; gbn = pgb[(s+1)*65536]; }
        ull a0e=0,a0o=0,a1e=0,a1o=0, c0e=0,c0o=0,c1e=0,c1o=0;
        const ulonglong2* hpa = reinterpret_cast<const ulonglong2*>(&hs[cur*512 + n*64]);
        const ulonglong2* hpb = reinterpret_cast<const ulonglong2*>(&hs[cur*512 + 256 + n*64]);
        #pragma unroll
        for (int hh = 0; hh < 16; hh++){
            ulonglong2 ha = hpa[hh];
            ulonglong2 hb = hpb[hh];
            a0e = fma2_(ha.x, r01[2*hh],   a0e);
            a1e = fma2_(ha.x, r23[2*hh],   a1e);
            c0e = fma2_(hb.x, r01[2*hh],   c0e);
            c1e = fma2_(hb.x, r23[2*hh],   c1e);
            a0o = fma2_(ha.y, r01[2*hh+1], a0o);
            a1o = fma2_(ha.y, r23[2*hh+1], a1o);
            c0o = fma2_(hb.y, r01[2*hh+1], c0o);
            c1o = fma2_(hb.y, r23[2*hh+1], c1o);
        }
        ull aa01 = add2_(a0e, a0o);
        ull aa23 = add2_(a1e, a1o);
        ull ab01 = add2_(c0e, c0o);
        ull ab23 = add2_(c1e, c1o);
        float ria,rfa,rza,roa, rib,rfb,rzb,rob;
        upk2(aa01,ria,rfa); upk2(aa23,rza,roa);
        upk2(ab01,rib,rfb); upk2(ab23,rzb,rob);
        float hn_a = slstm_step(ria+ga.x+bias0, rfa+ga.y+bias1, rza+ga.z+bias2, roa+ga.w+bias3, ca,na,ma);
        float hn_b = slstm_step(rib+gb.x+bias0, rfb+gb.y+bias1, rzb+gb.z+bias2, rob+gb.w+bias3, cb,nb,mb);
        int nxt = cur ^ 1;
        *reinterpret_cast<ull*>(&hs[nxt*512 + o*2])       = pk2(hn_a, hn_a);
        *reinterpret_cast<ull*>(&hs[nxt*512 + 256 + o*2]) = pk2(hn_b, hn_b);
        __syncwarp();
        float sa = hn_a, qa = hn_a*hn_a, sb2 = hn_b, qb = hn_b*hn_b;
        #pragma unroll
        for (int off=16; off>0; off>>=1){
            sa  += __shfl_xor_sync(0xffffffffu,sa,off);
            qa  += __shfl_xor_sync(0xffffffffu,qa,off);
            sb2 += __shfl_xor_sync(0xffffffffu,sb2,off);
            qb  += __shfl_xor_sync(0xffffffffu,qb,off);
        }
        float mua = sa*(1.f/32.f);
        float inva = rsqrtf(qa*(1.f/32.f) - mua*mua + EPSm);
        float mub = sb2*(1.f/32.f);
        float invb = rsqrtf(qb*(1.f/32.f) - mub*mub + EPSm);
        hpA[s*Dm] = hresA + (hn_a - mua)*inva*gw;
        hpB[s*Dm] = hresB + (hn_b - mub)*invb*gw;
        ga = gan; gb = gbn;
        cur = nxt;
    }
}

// ---------------- final LN + vocab projection ----------------
__global__ void k_proj(const float* __restrict__ pw_ln, const float* __restrict__ pjw,
                       const float* __restrict__ pjb, float* __restrict__ out){
    int gt = blockIdx.x*8 + (threadIdx.x>>5);
    int lane = threadIdx.x & 31;
    float4 v = reinterpret_cast<const float4*>(g_h + (size_t)gt*Dm)[lane];
    float s = v.x+v.y+v.z+v.w;
    float q = v.x*v.x+v.y*v.y+v.z*v.z+v.w*v.w;
    #pragma unroll
    for (int o=16;o>0;o>>=1){ s += __shfl_xor_sync(0xffffffffu,s,o); q += __shfl_xor_sync(0xffffffffu,q,o); }
    float mu = s*(1.f/128.f);
    float inv = rsqrtf(q*(1.f/128.f) - mu*mu + EPSm);
    float4 wv = reinterpret_cast<const float4*>(pw_ln)[lane];
    float4 xv;
    xv.x=(v.x-mu)*inv*wv.x; xv.y=(v.y-mu)*inv*wv.y;
    xv.z=(v.z-mu)*inv*wv.z; xv.w=(v.w-mu)*inv*wv.w;
    float res = 0.f;
    #pragma unroll
    for (int vc = 0; vc < 9; vc++){
        float4 p = reinterpret_cast<const float4*>(pjw + vc*Dm)[lane];
        float sv = xv.x*p.x + xv.y*p.y + xv.z*p.z + xv.w*p.w;
        #pragma unroll
        for (int o=16;o>0;o>>=1) sv += __shfl_xor_sync(0xffffffffu,sv,o);
        if (lane == vc) res = sv;
    }
    if (lane < 9) out[gt*9 + lane] = res + pjb[lane];
}

// ---------------- launch ----------------
extern "C" void kernel_launch(void* const* d_in, const int* in_sizes, int n_in,
                              void* d_out, int out_size){
    const int*   x      = (const int*)  d_in[0];
    const float* emb    = (const float*)d_in[1];
    const float* ln1_w  = (const float*)d_in[2];
    const float* Wg     = (const float*)d_in[3];
    const float* R      = (const float*)d_in[4];
    const float* bias   = (const float*)d_in[5];
    const float* gn_w   = (const float*)d_in[6];
    const float* ln2_w  = (const float*)d_in[7];
    const float* ffu    = (const float*)d_in[8];
    const float* ffd    = (const float*)d_in[9];
    const float* post_w = (const float*)d_in[10];
    const float* pjw    = (const float*)d_in[11];
    const float* pjb    = (const float*)d_in[12];
    float* out = (float*)d_out;

    cudaFuncSetAttribute(k_gx,   cudaFuncAttributeMaxDynamicSharedMemorySize, GXS_SMEM);
    cudaFuncSetAttribute(k_up,   cudaFuncAttributeMaxDynamicSharedMemorySize, UPS_SMEM);
    cudaFuncSetAttribute(k_down, cudaFuncAttributeMaxDynamicSharedMemorySize, DNS_SMEM);

    k_pre<<<4608,256>>>(x, emb, Wg, ffu, ffd);
    for (int bi = 0; bi < 2; bi++){
        k_gx  <<<128,512,GXS_SMEM>>>(bi, ln1_w + bi*Dm);
        k_scan<<<256,128>>>(R + bi*16384, bias + bi*512, gn_w + bi*Dm);
        k_up  <<<128,512,UPS_SMEM>>>(bi, ln2_w + bi*Dm);
        k_down<<<128,512,DNS_SMEM>>>(bi);
    }
    k_proj<<<4096,256>>>(post_w, pjw, pjb, out);
}

// round 12
// speedup vs baseline: 3.4128x; 1.0269x over previous
#include <cuda_runtime.h>
#include <cuda_bf16.h>
#include <math.h>
#include <stdint.h>
#include <cstdint>

#define Bm 512
#define Sm 64
#define Dm 128
#define EPSm 1e-5f
typedef unsigned long long ull;
typedef __nv_bfloat16 bf16;

// ---------------- scratch ----------------
__device__ float g_h[Bm*Sm*Dm];
__device__ float g_gx[(size_t)Sm*Bm*512];
__device__ __align__(16) bf16 g_vh[Bm*Sm*Dm], g_vl[Bm*Sm*Dm];
__device__ __align__(16) bf16 g_wgh[2*512*32],  g_wgl[2*512*32];   // [blk][o=n*128+k*4+g][h]
__device__ __align__(16) bf16 g_wuh[2*256*128], g_wul[2*256*128];  // [blk][out][in]
__device__ __align__(16) bf16 g_wdh[2*128*128], g_wdl[2*128*128];  // [blk][out][in]

// ---------------- f32x2 helpers (scan) ----------------
__device__ __forceinline__ ull pk2(float a, float b){ ull r; asm("mov.b64 %0, {%1,%2};" : "=l"(r) : "f"(a), "f"(b)); return r; }
__device__ __forceinline__ void upk2(ull v, float &a, float &b){ asm("mov.b64 {%0,%1}, %2;" : "=f"(a), "=f"(b) : "l"(v)); }
__device__ __forceinline__ ull fma2_(ull a, ull b, ull c){ ull d; asm("fma.rn.f32x2 %0, %1, %2, %3;" : "=l"(d) : "l"(a), "l"(b), "l"(c)); return d; }
__device__ __forceinline__ ull add2_(ull a, ull b){ ull d; asm("add.rn.f32x2 %0, %1, %2;" : "=l"(d) : "l"(a), "l"(b)); return d; }

// ---------------- mma helpers ----------------
__device__ __forceinline__ uint32_t s2u(const void* p){ return (uint32_t)__cvta_generic_to_shared(p); }
__device__ __forceinline__ void mma_bf16(float* c, const uint32_t* a, const uint32_t* b){
    asm("mma.sync.aligned.m16n8k16.row.col.f32.bf16.bf16.f32 "
        "{%0,%1,%2,%3}, {%4,%5,%6,%7}, {%8,%9}, {%0,%1,%2,%3};"
        : "+f"(c[0]), "+f"(c[1]), "+f"(c[2]), "+f"(c[3])
        : "r"(a[0]), "r"(a[1]), "r"(a[2]), "r"(a[3]), "r"(b[0]), "r"(b[1]));
}
__device__ __forceinline__ void ldsm4(uint32_t* r, uint32_t addr){
    asm volatile("ldmatrix.sync.aligned.m8n8.x4.shared.b16 {%0,%1,%2,%3}, [%4];"
        : "=r"(r[0]),"=r"(r[1]),"=r"(r[2]),"=r"(r[3]) : "r"(addr));
}
__device__ __forceinline__ void ldsm2(uint32_t* r, uint32_t addr){
    asm volatile("ldmatrix.sync.aligned.m8n8.x2.shared.b16 {%0,%1}, [%2];"
        : "=r"(r[0]),"=r"(r[1]) : "r"(addr));
}
__device__ __forceinline__ void mma3(float* c, const uint32_t* ah, const uint32_t* al,
                                     const uint32_t* bh, const uint32_t* bl){
    mma_bf16(c, ah, bh);
    mma_bf16(c, ah, bl);
    mma_bf16(c, al, bh);
}
__device__ __forceinline__ void bsplit(float x, bf16& h, bf16& l){
    h = __float2bfloat16(x);
    l = __float2bfloat16(x - __bfloat162float(h));
}
__device__ __forceinline__ float gelu_(float g){
    return 0.5f*g*(1.f + erff(g*0.70710678118f));
}

// LN one token (warp-collective) -> split bf16 into padded smem row (stride 136)
__device__ __forceinline__ void ln_row(const float* __restrict__ hrow, float4 lw, int lane,
                                       bf16* Ah, bf16* Al, int tok){
    float4 v = reinterpret_cast<const float4*>(hrow)[lane];
    float s = v.x+v.y+v.z+v.w;
    float q = v.x*v.x+v.y*v.y+v.z*v.z+v.w*v.w;
    #pragma unroll
    for (int o=16;o>0;o>>=1){ s += __shfl_xor_sync(0xffffffffu,s,o); q += __shfl_xor_sync(0xffffffffu,q,o); }
    float mu = s*(1.f/128.f);
    float inv = rsqrtf(q*(1.f/128.f) - mu*mu + EPSm);
    float x0=(v.x-mu)*inv*lw.x, x1=(v.y-mu)*inv*lw.y;
    float x2=(v.z-mu)*inv*lw.z, x3=(v.w-mu)*inv*lw.w;
    bf16 h0,l0,h1,l1,h2,l2,h3,l3;
    bsplit(x0,h0,l0); bsplit(x1,h1,l1); bsplit(x2,h2,l2); bsplit(x3,h3,l3);
    int base = tok*136 + lane*4;
    __nv_bfloat162 p0; p0.x=h0; p0.y=h1;
    __nv_bfloat162 p1; p1.x=h2; p1.y=h3;
    __nv_bfloat162 q0; q0.x=l0; q0.y=l1;
    __nv_bfloat162 q1; q1.x=l2; q1.y=l3;
    *reinterpret_cast<__nv_bfloat162*>(Ah+base)   = p0;
    *reinterpret_cast<__nv_bfloat162*>(Ah+base+2) = p1;
    *reinterpret_cast<__nv_bfloat162*>(Al+base)   = q0;
    *reinterpret_cast<__nv_bfloat162*>(Al+base+2) = q1;
}

// ---------------- fused embedding + weight prep ----------------
__global__ void k_pre(const int* __restrict__ x, const float* __restrict__ emb,
                      const float* __restrict__ wg, const float* __restrict__ wu,
                      const float* __restrict__ wd){
    if (blockIdx.x < 4096){
        int i = blockIdx.x*256 + threadIdx.x;
        int t = i >> 5, d4 = i & 31;
        int v = x[t];
        reinterpret_cast<float4*>(g_h)[t*32 + d4] =
            reinterpret_cast<const float4*>(emb)[v*32 + d4];
        return;
    }
    int id = (blockIdx.x - 4096)*256 + threadIdx.x;   // 131072 total
    if (id < 32768){
        int blk = id >> 14, rem = id & 16383;
        int o = rem >> 5, h = rem & 31;
        int n = o >> 7, r = o & 127, kk = r >> 2, g = r & 3;
        float val = wg[(((blk*4 + g)*4 + n)*32 + kk)*32 + h];
        bf16 hi, lo; bsplit(val, hi, lo);
        g_wgh[id] = hi; g_wgl[id] = lo;
    } else if (id < 98304){
        int t = id - 32768;
        bf16 hi, lo; bsplit(wu[t], hi, lo);
        g_wuh[t] = hi; g_wul[t] = lo;
    } else {
        int t = id - 98304;
        bf16 hi, lo; bsplit(wd[t], hi, lo);
        g_wdh[t] = hi; g_wdl[t] = lo;
    }
}

// ================= fused LN1 + gate GEMM =================
// grid 128, 1024 thr (32 warps), 256 tokens/CTA
// smem el: Ah 0 (256x136), Al 34816, Wh 69632 (512x40), Wl 90112; total 110592 el
#define GXS_SMEM (110592*2)
__global__ void __launch_bounds__(1024,1) k_gx(int blk, const float* __restrict__ lnw){
    extern __shared__ bf16 smg[];
    bf16 *Ah = smg, *Al = smg + 34816, *Wh = smg + 69632, *Wl = smg + 90112;
    int tid = threadIdx.x, w = tid>>5, lane = tid&31;
    const bf16* wh = g_wgh + blk*16384;
    const bf16* wl = g_wgl + blk*16384;
    for (int i = tid; i < 2048; i += 1024){
        int r = i>>2, c8 = (i&3)*8;
        *reinterpret_cast<uint4*>(Wh + r*40 + c8) = *reinterpret_cast<const uint4*>(wh + r*32 + c8);
        *reinterpret_cast<uint4*>(Wl + r*40 + c8) = *reinterpret_cast<const uint4*>(wl + r*32 + c8);
    }
    int t0 = blockIdx.x*256;
    float4 lw = reinterpret_cast<const float4*>(lnw)[lane];
    #pragma unroll 1
    for (int i = 0; i < 8; i++){
        int tok = w*8 + i;
        ln_row(g_h + (size_t)(t0+tok)*128, lw, lane, Ah, Al, tok);
    }
    __syncthreads();

    int gr = lane>>2, gc = (lane&3)*2;
    int r7 = lane&7, g2 = (lane>>3)&1, g4 = lane>>4;
    uint32_t aoff = (uint32_t)(((g2*8 + r7)*136 + g4*8)*2);
    uint32_t boff = (uint32_t)((r7*40 + g2*8)*2);
    uint32_t sAh = s2u(Ah), sAl = s2u(Al), sWh = s2u(Wh), sWl = s2u(Wl);
    int m0 = (w&7)*32;
    int nquad = w>>3;                       // 0..3
    #pragma unroll 1
    for (int it = 0; it < 2; it++){
        int ng = nquad*2 + it;              // 0..7
        int head = ng>>1;
        int nb = ng*64;
        float acc[2][8][4];
        #pragma unroll
        for (int ms=0;ms<2;ms++)
            #pragma unroll
            for (int nt=0;nt<8;nt++)
                #pragma unroll
                for (int i=0;i<4;i++) acc[ms][nt][i]=0.f;
        #pragma unroll
        for (int kc = 0; kc < 2; kc++){
            int k0 = head*32 + kc*16;
            uint32_t ab = (uint32_t)((m0*136 + k0)*2);
            uint32_t ah0[4], ah1[4], al0[4], al1[4];
            ldsm4(ah0, sAh + ab + aoff);
            ldsm4(ah1, sAh + ab + 16u*136u*2u + aoff);
            ldsm4(al0, sAl + ab + aoff);
            ldsm4(al1, sAl + ab + 16u*136u*2u + aoff);
            uint32_t wb0 = (uint32_t)(kc*16*2);
            #pragma unroll
            for (int nt = 0; nt < 8; nt++){
                int nr = nb + nt*8;
                uint32_t bb = (uint32_t)(nr*40*2) + wb0 + boff;
                uint32_t bh[2], bl[2];
                ldsm2(bh, sWh + bb);
                ldsm2(bl, sWl + bb);
                mma3(acc[0][nt], ah0, al0, bh, bl);
                mma3(acc[1][nt], ah1, al1, bh, bl);
            }
        }
        #pragma unroll
        for (int ms=0;ms<2;ms++){
            int tA = t0 + m0 + ms*16 + gr;
            int tB = tA + 8;
            int bA = tA>>6, sA = tA&63;
            int bB = tB>>6, sB = tB&63;
            float* dA = &g_gx[((size_t)(sA*Bm + bA))*512];
            float* dB = &g_gx[((size_t)(sB*Bm + bB))*512];
            #pragma unroll
            for (int nt=0;nt<8;nt++){
                int col = nb + nt*8 + gc;
                *reinterpret_cast<float2*>(dA + col) = make_float2(acc[ms][nt][0], acc[ms][nt][1]);
                *reinterpret_cast<float2*>(dB + col) = make_float2(acc[ms][nt][2], acc[ms][nt][3]);
            }
        }
    }
}

// ================= fused LN2 + FF up + GeGLU -> split v =================
// grid 128, 1024 thr (32 warps), 2 m-tiles of 128 tokens
// smem el: Ah 0 (128x136), Al 17408, Wh 34816 (256x136), Wl 69632; total 104448 el
#define UPS_SMEM (104448*2)
__global__ void __launch_bounds__(1024,1) k_up(int blk, const float* __restrict__ lnw){
    extern __shared__ bf16 smu[];
    bf16 *Ah = smu, *Al = smu + 17408, *Wh = smu + 34816, *Wl = smu + 69632;
    int tid = threadIdx.x, w = tid>>5, lane = tid&31;
    const bf16* wh = g_wuh + blk*32768;
    const bf16* wl = g_wul + blk*32768;
    for (int i = tid; i < 4096; i += 1024){
        int r = i>>4, c8 = (i&15)*8;
        *reinterpret_cast<uint4*>(Wh + r*136 + c8) = *reinterpret_cast<const uint4*>(wh + r*128 + c8);
        *reinterpret_cast<uint4*>(Wl + r*136 + c8) = *reinterpret_cast<const uint4*>(wl + r*128 + c8);
    }
    float4 lw = reinterpret_cast<const float4*>(lnw)[lane];
    int gr = lane>>2, gc = (lane&3)*2;
    int r7 = lane&7, g2 = (lane>>3)&1, g4 = lane>>4;
    uint32_t aoff = (uint32_t)(((g2*8 + r7)*136 + g4*8)*2);
    uint32_t boff = (uint32_t)((r7*136 + g2*8)*2);
    uint32_t sAh = s2u(Ah), sAl = s2u(Al), sWh = s2u(Wh), sWl = s2u(Wl);
    int m0 = (w&3)*32;
    int j0 = (w>>2)*16;                    // 8 j-groups of 16
    #pragma unroll 1
    for (int mt = 0; mt < 2; mt++){
        int t0 = (blockIdx.x*2 + mt)*128;
        __syncthreads();
        #pragma unroll 1
        for (int i = 0; i < 4; i++){
            int tok = w*4 + i;
            ln_row(g_h + (size_t)(t0+tok)*128, lw, lane, Ah, Al, tok);
        }
        __syncthreads();
        float ga[2][2][4], ua[2][2][4];
        #pragma unroll
        for (int ms=0;ms<2;ms++)
            #pragma unroll
            for (int nt=0;nt<2;nt++)
                #pragma unroll
                for (int i=0;i<4;i++){ ga[ms][nt][i]=0.f; ua[ms][nt][i]=0.f; }
        #pragma unroll
        for (int kc = 0; kc < 8; kc++){
            int k0 = kc*16;
            uint32_t ab = (uint32_t)((m0*136 + k0)*2);
            uint32_t ah0[4], ah1[4], al0[4], al1[4];
            ldsm4(ah0, sAh + ab + aoff);
            ldsm4(ah1, sAh + ab + 16u*136u*2u + aoff);
            ldsm4(al0, sAl + ab + aoff);
            ldsm4(al1, sAl + ab + 16u*136u*2u + aoff);
            #pragma unroll
            for (int nt = 0; nt < 2; nt++){
                int jr = j0 + nt*8;
                uint32_t bbg = (uint32_t)((jr*136 + k0)*2) + boff;
                uint32_t bbu = (uint32_t)(((128+jr)*136 + k0)*2) + boff;
                uint32_t bgh[2], bgl[2], buh[2], bul[2];
                ldsm2(bgh, sWh + bbg);
                ldsm2(bgl, sWl + bbg);
                ldsm2(buh, sWh + bbu);
                ldsm2(bul, sWl + bbu);
                mma3(ga[0][nt], ah0, al0, bgh, bgl);
                mma3(ga[1][nt], ah1, al1, bgh, bgl);
                mma3(ua[0][nt], ah0, al0, buh, bul);
                mma3(ua[1][nt], ah1, al1, buh, bul);
            }
        }
        #pragma unroll
        for (int ms=0;ms<2;ms++){
            size_t rA = (size_t)(t0 + m0 + ms*16 + gr)*128;
            size_t rB = rA + 8*128;
            #pragma unroll
            for (int nt=0;nt<2;nt++){
                int col = j0 + nt*8 + gc;
                float v0 = gelu_(ga[ms][nt][0])*ua[ms][nt][0];
                float v1 = gelu_(ga[ms][nt][1])*ua[ms][nt][1];
                float v2 = gelu_(ga[ms][nt][2])*ua[ms][nt][2];
                float v3 = gelu_(ga[ms][nt][3])*ua[ms][nt][3];
                bf16 h0,l0,h1,l1,h2,l2,h3,l3;
                bsplit(v0,h0,l0); bsplit(v1,h1,l1); bsplit(v2,h2,l2); bsplit(v3,h3,l3);
                __nv_bfloat162 p0; p0.x=h0; p0.y=h1;
                __nv_bfloat162 p1; p1.x=h2; p1.y=h3;
                __nv_bfloat162 q0; q0.x=l0; q0.y=l1;
                __nv_bfloat162 q1; q1.x=l2; q1.y=l3;
                *reinterpret_cast<__nv_bfloat162*>(&g_vh[rA + col]) = p0;
                *reinterpret_cast<__nv_bfloat162*>(&g_vh[rB + col]) = p1;
                *reinterpret_cast<__nv_bfloat162*>(&g_vl[rA + col]) = q0;
                *reinterpret_cast<__nv_bfloat162*>(&g_vl[rB + col]) = q1;
            }
        }
    }
}

// ================= FF down + residual =================
// grid 128, 1024 thr (32 warps), 2 m-tiles of 128 tokens
// smem el: Ah 0, Al 17408, Wh 34816 (128x136), Wl 52224; total 69632 el
#define DNS_SMEM (69632*2)
__global__ void __launch_bounds__(1024,1) k_down(int blk){
    extern __shared__ bf16 smd[];
    bf16 *Ah = smd, *Al = smd + 17408, *Wh = smd + 34816, *Wl = smd + 52224;
    int tid = threadIdx.x, w = tid>>5, lane = tid&31;
    const bf16* wh = g_wdh + blk*16384;
    const bf16* wl = g_wdl + blk*16384;
    for (int i = tid; i < 2048; i += 1024){
        int r = i>>4, c8 = (i&15)*8;
        *reinterpret_cast<uint4*>(Wh + r*136 + c8) = *reinterpret_cast<const uint4*>(wh + r*128 + c8);
        *reinterpret_cast<uint4*>(Wl + r*136 + c8) = *reinterpret_cast<const uint4*>(wl + r*128 + c8);
    }
    int gr = lane>>2, gc = (lane&3)*2;
    int r7 = lane&7, g2 = (lane>>3)&1, g4 = lane>>4;
    uint32_t aoff = (uint32_t)(((g2*8 + r7)*136 + g4*8)*2);
    uint32_t boff = (uint32_t)((r7*136 + g2*8)*2);
    uint32_t sAh = s2u(Ah), sAl = s2u(Al), sWh = s2u(Wh), sWl = s2u(Wl);
    int m0 = (w&3)*32;
    int nb = (w>>2)*16;                    // 8 n-groups of 16
    #pragma unroll 1
    for (int mt = 0; mt < 2; mt++){
        int t0 = (blockIdx.x*2 + mt)*128;
        __syncthreads();
        for (int i = tid; i < 2048; i += 1024){
            int r = i>>4, c8 = (i&15)*8;
            *reinterpret_cast<uint4*>(Ah + r*136 + c8) = *reinterpret_cast<const uint4*>(g_vh + (size_t)(t0+r)*128 + c8);
            *reinterpret_cast<uint4*>(Al + r*136 + c8) = *reinterpret_cast<const uint4*>(g_vl + (size_t)(t0+r)*128 + c8);
        }
        __syncthreads();
        float acc[2][2][4];
        #pragma unroll
        for (int ms=0;ms<2;ms++)
            #pragma unroll
            for (int nt=0;nt<2;nt++)
                #pragma unroll
                for (int i=0;i<4;i++) acc[ms][nt][i]=0.f;
        #pragma unroll
        for (int kc = 0; kc < 8; kc++){
            int k0 = kc*16;
            uint32_t ab = (uint32_t)((m0*136 + k0)*2);
            uint32_t ah0[4], ah1[4], al0[4], al1[4];
            ldsm4(ah0, sAh + ab + aoff);
            ldsm4(ah1, sAh + ab + 16u*136u*2u + aoff);
            ldsm4(al0, sAl + ab + aoff);
            ldsm4(al1, sAl + ab + 16u*136u*2u + aoff);
            #pragma unroll
            for (int nt = 0; nt < 2; nt++){
                int nr = nb + nt*8;
                uint32_t bb = (uint32_t)((nr*136 + k0)*2) + boff;
                uint32_t bh[2], bl[2];
                ldsm2(bh, sWh + bb);
                ldsm2(bl, sWl + bb);
                mma3(acc[0][nt], ah0, al0, bh, bl);
                mma3(acc[1][nt], ah1, al1, bh, bl);
            }
        }
        #pragma unroll
        for (int ms=0;ms<2;ms++){
            size_t rA = (size_t)(t0 + m0 + ms*16 + gr)*128;
            size_t rB = rA + 8*128;
            #pragma unroll
            for (int nt=0;nt<2;nt++){
                int col = nb + nt*8 + gc;
                float2* pA = reinterpret_cast<float2*>(&g_h[rA + col]);
                float2* pB = reinterpret_cast<float2*>(&g_h[rB + col]);
                float2 hA = *pA, hB = *pB;
                hA.x += acc[ms][nt][0]; hA.y += acc[ms][nt][1];
                hB.x += acc[ms][nt][2]; hB.y += acc[ms][nt][3];
                *pA = hA; *pB = hB;
            }
        }
    }
}

// ---------------- sLSTM gate math (branchless) ----------------
__device__ __forceinline__ float slstm_step(float i_r, float f_r, float z_r, float o_r,
                                            float& c, float& nn, float& m){
    float lsf = fminf(f_r, 0.f) - __logf(1.f + __expf(-fabsf(f_r)));
    float lfm = m + lsf;
    float mnew = fmaxf(i_r, lfm);
    float ig = __expf(i_r - mnew);
    float fg = __expf(lfm - mnew);
    float e2z = __expf(2.f*z_r);
    float tz = 1.f - __fdividef(2.f, e2z + 1.f);
    c  = fg*c  + ig*tz;
    nn = fg*nn + ig;
    m  = mnew;
    float so = __fdividef(1.f, 1.f + __expf(-o_r));
    return so * __fdividef(c, nn);
}

// ================= sequential scan =================
__global__ void __launch_bounds__(128,2) k_scan(const float* __restrict__ Rw,
                                                const float* __restrict__ bw,
                                                const float* __restrict__ gnw){
    __shared__ __align__(16) float hs[1024];
    int tid = threadIdx.x;
    int n = tid >> 5, k = tid & 31;
    int b0 = blockIdx.x*2, b1 = b0 + 1;

    ull r01[32], r23[32];
    const float* rp = Rw + n*4096 + k;
    #pragma unroll
    for (int h = 0; h < 32; h++){
        r01[h] = pk2(rp[h*128],      rp[h*128 + 32]);
        r23[h] = pk2(rp[h*128 + 64], rp[h*128 + 96]);
    }
    float bias0 = bw[(n*4+0)*32+k], bias1 = bw[(n*4+1)*32+k];
    float bias2 = bw[(n*4+2)*32+k], bias3 = bw[(n*4+3)*32+k];
    float gw = gnw[n*32+k];

    int o = n*32 + k;
    *reinterpret_cast<ull*>(&hs[o*2])       = 0ull;
    *reinterpret_cast<ull*>(&hs[256 + o*2]) = 0ull;
    float ca=0.f, na=0.f, ma=0.f, cb=0.f, nb=0.f, mb=0.f;
    __syncwarp();

    const float4* pga = reinterpret_cast<const float4*>(&g_gx[(size_t)b0*512 + o*4]);
    const float4* pgb = reinterpret_cast<const float4*>(&g_gx[(size_t)b1*512 + o*4]);
    float* hpA = &g_h[(size_t)(b0*64)*Dm + o];
    float* hpB = &g_h[(size_t)(b1*64)*Dm + o];
    float4 ga = pga[0], gb = pgb[0];
    int cur = 0;

    for (int s = 0; s < Sm; s++){
        float hresA = hpA[s*Dm];
        float hresB = hpB[s*Dm];
        float4 gan = ga, gbn = gb;
        if (s < Sm-1){ gan = pga[(s+1)*65536]; gbn = pgb[(s+1)*65536]; }
        ull a0e=0,a0o=0,a1e=0,a1o=0, c0e=0,c0o=0,c1e=0,c1o=0;
        const ulonglong2* hpa = reinterpret_cast<const ulonglong2*>(&hs[cur*512 + n*64]);
        const ulonglong2* hpb = reinterpret_cast<const ulonglong2*>(&hs[cur*512 + 256 + n*64]);
        #pragma unroll
        for (int hh = 0; hh < 16; hh++){
            ulonglong2 ha = hpa[hh];
            ulonglong2 hb = hpb[hh];
            a0e = fma2_(ha.x, r01[2*hh],   a0e);
            a1e = fma2_(ha.x, r23[2*hh],   a1e);
            c0e = fma2_(hb.x, r01[2*hh],   c0e);
            c1e = fma2_(hb.x, r23[2*hh],   c1e);
            a0o = fma2_(ha.y, r01[2*hh+1], a0o);
            a1o = fma2_(ha.y, r23[2*hh+1], a1o);
            c0o = fma2_(hb.y, r01[2*hh+1], c0o);
            c1o = fma2_(hb.y, r23[2*hh+1], c1o);
        }
        ull aa01 = add2_(a0e, a0o);
        ull aa23 = add2_(a1e, a1o);
        ull ab01 = add2_(c0e, c0o);
        ull ab23 = add2_(c1e, c1o);
        float ria,rfa,rza,roa, rib,rfb,rzb,rob;
        upk2(aa01,ria,rfa); upk2(aa23,rza,roa);
        upk2(ab01,rib,rfb); upk2(ab23,rzb,rob);
        float hn_a = slstm_step(ria+ga.x+bias0, rfa+ga.y+bias1, rza+ga.z+bias2, roa+ga.w+bias3, ca,na,ma);
        float hn_b = slstm_step(rib+gb.x+bias0, rfb+gb.y+bias1, rzb+gb.z+bias2, rob+gb.w+bias3, cb,nb,mb);
        int nxt = cur ^ 1;
        *reinterpret_cast<ull*>(&hs[nxt*512 + o*2])       = pk2(hn_a, hn_a);
        *reinterpret_cast<ull*>(&hs[nxt*512 + 256 + o*2]) = pk2(hn_b, hn_b);
        __syncwarp();
        float sa = hn_a, qa = hn_a*hn_a, sb2 = hn_b, qb = hn_b*hn_b;
        #pragma unroll
        for (int off=16; off>0; off>>=1){
            sa  += __shfl_xor_sync(0xffffffffu,sa,off);
            qa  += __shfl_xor_sync(0xffffffffu,qa,off);
            sb2 += __shfl_xor_sync(0xffffffffu,sb2,off);
            qb  += __shfl_xor_sync(0xffffffffu,qb,off);
        }
        float mua = sa*(1.f/32.f);
        float inva = rsqrtf(qa*(1.f/32.f) - mua*mua + EPSm);
        float mub = sb2*(1.f/32.f);
        float invb = rsqrtf(qb*(1.f/32.f) - mub*mub + EPSm);
        hpA[s*Dm] = hresA + (hn_a - mua)*inva*gw;
        hpB[s*Dm] = hresB + (hn_b - mub)*invb*gw;
        ga = gan; gb = gbn;
        cur = nxt;
    }
}

// ---------------- final LN + vocab projection ----------------
__global__ void k_proj(const float* __restrict__ pw_ln, const float* __restrict__ pjw,
                       const float* __restrict__ pjb, float* __restrict__ out){
    int gt = blockIdx.x*8 + (threadIdx.x>>5);
    int lane = threadIdx.x & 31;
    float4 v = reinterpret_cast<const float4*>(g_h + (size_t)gt*Dm)[lane];
    float s = v.x+v.y+v.z+v.w;
    float q = v.x*v.x+v.y*v.y+v.z*v.z+v.w*v.w;
    #pragma unroll
    for (int o=16;o>0;o>>=1){ s += __shfl_xor_sync(0xffffffffu,s,o); q += __shfl_xor_sync(0xffffffffu,q,o); }
    float mu = s*(1.f/128.f);
    float inv = rsqrtf(q*(1.f/128.f) - mu*mu + EPSm);
    float4 wv = reinterpret_cast<const float4*>(pw_ln)[lane];
    float4 xv;
    xv.x=(v.x-mu)*inv*wv.x; xv.y=(v.y-mu)*inv*wv.y;
    xv.z=(v.z-mu)*inv*wv.z; xv.w=(v.w-mu)*inv*wv.w;
    float res = 0.f;
    #pragma unroll
    for (int vc = 0; vc < 9; vc++){
        float4 p = reinterpret_cast<const float4*>(pjw + vc*Dm)[lane];
        float sv = xv.x*p.x + xv.y*p.y + xv.z*p.z + xv.w*p.w;
        #pragma unroll
        for (int o=16;o>0;o>>=1) sv += __shfl_xor_sync(0xffffffffu,sv,o);
        if (lane == vc) res = sv;
    }
    if (lane < 9) out[gt*9 + lane] = res + pjb[lane];
}

// ---------------- launch ----------------
extern "C" void kernel_launch(void* const* d_in, const int* in_sizes, int n_in,
                              void* d_out, int out_size){
    const int*   x      = (const int*)  d_in[0];
    const float* emb    = (const float*)d_in[1];
    const float* ln1_w  = (const float*)d_in[2];
    const float* Wg     = (const float*)d_in[3];
    const float* R      = (const float*)d_in[4];
    const float* bias   = (const float*)d_in[5];
    const float* gn_w   = (const float*)d_in[6];
    const float* ln2_w  = (const float*)d_in[7];
    const float* ffu    = (const float*)d_in[8];
    const float* ffd    = (const float*)d_in[9];
    const float* post_w = (const float*)d_in[10];
    const float* pjw    = (const float*)d_in[11];
    const float* pjb    = (const float*)d_in[12];
    float* out = (float*)d_out;

    cudaFuncSetAttribute(k_gx,   cudaFuncAttributeMaxDynamicSharedMemorySize, GXS_SMEM);
    cudaFuncSetAttribute(k_up,   cudaFuncAttributeMaxDynamicSharedMemorySize, UPS_SMEM);
    cudaFuncSetAttribute(k_down, cudaFuncAttributeMaxDynamicSharedMemorySize, DNS_SMEM);

    k_pre<<<4608,256>>>(x, emb, Wg, ffu, ffd);
    for (int bi = 0; bi < 2; bi++){
        k_gx  <<<128,1024,GXS_SMEM>>>(bi, ln1_w + bi*Dm);
        k_scan<<<256,128>>>(R + bi*16384, bias + bi*512, gn_w + bi*Dm);
        k_up  <<<128,1024,UPS_SMEM>>>(bi, ln2_w + bi*Dm);
        k_down<<<128,1024,DNS_SMEM>>>(bi);
    }
    k_proj<<<4096,256>>>(post_w, pjw, pjb, out);
}